// round 1
// baseline (speedup 1.0000x reference)
#include <cuda_runtime.h>
#include <cuda_bf16.h>
#include <math.h>

#define V_N 20000
#define E_N 100000
#define NODE_IN 128
#define EDGE_IN 128
#define HF 64
#define EDGE_HID 128
#define OUTF 64
#define STEPS 9

// ---------------- scratch (device globals; no allocations allowed) ----------
__device__ float g_h[V_N * HF];                    // node state (h == hidden)
__device__ float g_r[E_N * EDGE_HID];              // relu(edge layer1)
__device__ float g_We[(size_t)E_N * HF * HF];      // per-edge 64x64 matrices (1.64 GB)
__device__ float g_agg[V_N * HF];                  // scatter accumulator

// ---------------- project: h = relu(X@w1^T+b1)@w2^T+b2 ----------------------
__global__ void project_kernel(const float* __restrict__ X,
                               const float* __restrict__ w1, const float* __restrict__ b1,
                               const float* __restrict__ w2, const float* __restrict__ b2,
                               float* __restrict__ Hout) {
    __shared__ float xs[NODE_IN];
    __shared__ float hs[HF];
    int v = blockIdx.x;
    int t = threadIdx.x; // 64 threads
    xs[t]      = X[v * NODE_IN + t];
    xs[t + 64] = X[v * NODE_IN + t + 64];
    __syncthreads();
    float acc = b1[t];
#pragma unroll 8
    for (int i = 0; i < NODE_IN; i++) acc += w1[t * NODE_IN + i] * xs[i];
    hs[t] = fmaxf(acc, 0.f);
    __syncthreads();
    float acc2 = b2[t];
#pragma unroll 8
    for (int i = 0; i < HF; i++) acc2 += w2[t * HF + i] * hs[i];
    Hout[v * HF + t] = acc2;
}

// ---------------- generic SGEMM: C(MxN) = A(MxK) @ W(NxK)^T + bias ----------
// BM=64, BN=128, BK=16, TM=4, TN=8, 256 threads
template <bool RELU>
__global__ void sgemm_bias(const float* __restrict__ A,
                           const float* __restrict__ W,
                           const float* __restrict__ bias,
                           float* __restrict__ C,
                           int M, int N, int K) {
    const int BM = 64, BN = 128, BK = 16, TM = 4, TN = 8;
    __shared__ float As[BK][BM];
    __shared__ float Bs[BK][BN];
    const int tid = threadIdx.x;
    const int m0 = blockIdx.y * BM;
    const int n0 = blockIdx.x * BN;
    const int tx = tid % (BN / TN);  // 0..15
    const int ty = tid / (BN / TN);  // 0..15
    float acc[TM][TN];
#pragma unroll
    for (int i = 0; i < TM; i++)
#pragma unroll
        for (int j = 0; j < TN; j++) acc[i][j] = 0.f;

    for (int k0 = 0; k0 < K; k0 += BK) {
#pragma unroll
        for (int idx = tid; idx < BM * BK; idx += 256) {
            int k = idx % BK, m = idx / BK;
            As[k][m] = (m0 + m < M) ? A[(size_t)(m0 + m) * K + k0 + k] : 0.f;
        }
#pragma unroll
        for (int idx = tid; idx < BN * BK; idx += 256) {
            int k = idx % BK, n = idx / BK;
            Bs[k][n] = W[(size_t)(n0 + n) * K + k0 + k];
        }
        __syncthreads();
#pragma unroll
        for (int k = 0; k < BK; k++) {
            float a[TM], b[TN];
#pragma unroll
            for (int i = 0; i < TM; i++) a[i] = As[k][ty * TM + i];
#pragma unroll
            for (int j = 0; j < TN; j++) b[j] = Bs[k][tx * TN + j];
#pragma unroll
            for (int i = 0; i < TM; i++)
#pragma unroll
                for (int j = 0; j < TN; j++) acc[i][j] += a[i] * b[j];
        }
        __syncthreads();
    }
#pragma unroll
    for (int i = 0; i < TM; i++) {
        int m = m0 + ty * TM + i;
        if (m >= M) continue;
#pragma unroll
        for (int j = 0; j < TN; j++) {
            int n = n0 + tx * TN + j;
            float v = acc[i][j] + bias[n];
            if (RELU) v = fmaxf(v, 0.f);
            C[(size_t)m * N + n] = v;
        }
    }
}

// ---------------- per-edge matvec + scatter ---------------------------------
// 256 threads = 4 edges x 64 output features
__global__ void msg_kernel(const float* __restrict__ h,
                           const int* __restrict__ src, const int* __restrict__ dst,
                           const float* __restrict__ We,
                           float* __restrict__ agg, int E) {
    int sub = threadIdx.x >> 6;
    int o = threadIdx.x & 63;
    int e = blockIdx.x * 4 + sub;
    __shared__ float hs[4][HF];
    if (e < E) hs[sub][o] = h[src[e] * HF + o];
    __syncthreads();
    if (e >= E) return;
    const float* hp = hs[sub];
    const float* Wp = We + (size_t)e * (HF * HF) + o;
    float acc = 0.f;
#pragma unroll
    for (int i = 0; i < HF; i++) acc += hp[i] * Wp[(size_t)i * HF];
    atomicAdd(&agg[dst[e] * HF + o], acc);
}

// ---------------- GRU cell (in-place state update) --------------------------
// 256 threads = 4 nodes x 64 features
__global__ void gru_kernel(const float* __restrict__ agg, const float* __restrict__ b_conv,
                           const float* __restrict__ w_ih, const float* __restrict__ w_hh,
                           const float* __restrict__ b_ih, const float* __restrict__ b_hh,
                           float* __restrict__ hbuf, int V) {
    int n = threadIdx.x >> 6;
    int o = threadIdx.x & 63;
    int v = blockIdx.x * 4 + n;
    __shared__ float xs[4][HF], hh[4][HF];
    if (v < V) {
        xs[n][o] = fmaxf(agg[v * HF + o] + b_conv[o], 0.f);
        hh[n][o] = hbuf[v * HF + o];
    }
    __syncthreads();
    if (v >= V) return;
    float ir = b_ih[o], iz = b_ih[HF + o], in_ = b_ih[2 * HF + o];
    float hr = b_hh[o], hz = b_hh[HF + o], hn = b_hh[2 * HF + o];
    const float* x = xs[n];
    const float* hv = hh[n];
#pragma unroll 8
    for (int j = 0; j < HF; j++) {
        float xj = x[j], hj = hv[j];
        ir += w_ih[o * HF + j] * xj;
        iz += w_ih[(HF + o) * HF + j] * xj;
        in_ += w_ih[(2 * HF + o) * HF + j] * xj;
        hr += w_hh[o * HF + j] * hj;
        hz += w_hh[(HF + o) * HF + j] * hj;
        hn += w_hh[(2 * HF + o) * HF + j] * hj;
    }
    float r = 1.f / (1.f + expf(-(ir + hr)));
    float z = 1.f / (1.f + expf(-(iz + hz)));
    float nn = tanhf(in_ + r * hn);
    hbuf[v * HF + o] = (1.f - z) * nn + z * hv[o];
}

// ---------------- decoder ---------------------------------------------------
__global__ void decoder_kernel(const float* __restrict__ hbuf,
                               const float* __restrict__ w1, const float* __restrict__ b1,
                               const float* __restrict__ w2, const float* __restrict__ b2,
                               float* __restrict__ out) {
    __shared__ float hs[HF], mid[HF];
    int v = blockIdx.x;
    int t = threadIdx.x; // 64
    hs[t] = hbuf[v * HF + t];
    __syncthreads();
    float a = b1[t];
#pragma unroll 8
    for (int j = 0; j < HF; j++) a += w1[t * HF + j] * hs[j];
    mid[t] = fmaxf(a, 0.f);
    __syncthreads();
    float a2 = b2[t];
#pragma unroll 8
    for (int j = 0; j < HF; j++) a2 += w2[t * HF + j] * mid[j];
    out[v * OUTF + t] = a2;
}

// ---------------- host launch ------------------------------------------------
extern "C" void kernel_launch(void* const* d_in, const int* in_sizes, int n_in,
                              void* d_out, int out_size) {
    const float* node_feats = (const float*)d_in[0];
    const float* edge_feats = (const float*)d_in[1];
    const int* src = (const int*)d_in[2];
    const int* dst = (const int*)d_in[3];
    const float* w_p1 = (const float*)d_in[4];
    const float* b_p1 = (const float*)d_in[5];
    const float* w_p2 = (const float*)d_in[6];
    const float* b_p2 = (const float*)d_in[7];
    const float* w_e1 = (const float*)d_in[8];
    const float* b_e1 = (const float*)d_in[9];
    const float* w_e2 = (const float*)d_in[10];
    const float* b_e2 = (const float*)d_in[11];
    const float* b_conv = (const float*)d_in[12];
    const float* w_ih = (const float*)d_in[13];
    const float* w_hh = (const float*)d_in[14];
    const float* b_ih = (const float*)d_in[15];
    const float* b_hh = (const float*)d_in[16];
    const float* w_d1 = (const float*)d_in[17];
    const float* b_d1 = (const float*)d_in[18];
    const float* w_d2 = (const float*)d_in[19];
    const float* b_d2 = (const float*)d_in[20];
    float* out = (float*)d_out;

    const int V = in_sizes[0] / NODE_IN;
    const int E = in_sizes[2];

    float *h_ptr, *r_ptr, *We_ptr, *agg_ptr;
    cudaGetSymbolAddress((void**)&h_ptr, g_h);
    cudaGetSymbolAddress((void**)&r_ptr, g_r);
    cudaGetSymbolAddress((void**)&We_ptr, g_We);
    cudaGetSymbolAddress((void**)&agg_ptr, g_agg);

    // 1) project node feats
    project_kernel<<<V, 64>>>(node_feats, w_p1, b_p1, w_p2, b_p2, h_ptr);

    // 2) edge network layer 1: r = relu(edge @ w_e1^T + b_e1), E x 128
    {
        dim3 grid(EDGE_HID / 128, (E + 63) / 64);
        sgemm_bias<true><<<grid, 256>>>(edge_feats, w_e1, b_e1, r_ptr, E, EDGE_HID, EDGE_IN);
    }
    // 3) edge network layer 2: We = r @ w_e2^T + b_e2, E x 4096 (static, once)
    {
        dim3 grid((HF * HF) / 128, (E + 63) / 64);
        sgemm_bias<false><<<grid, 256>>>(r_ptr, w_e2, b_e2, We_ptr, E, HF * HF, EDGE_HID);
    }

    // 4) message passing loop
    for (int s = 0; s < STEPS; s++) {
        cudaMemsetAsync(agg_ptr, 0, (size_t)V * HF * sizeof(float));
        msg_kernel<<<(E + 3) / 4, 256>>>(h_ptr, src, dst, We_ptr, agg_ptr, E);
        gru_kernel<<<(V + 3) / 4, 256>>>(agg_ptr, b_conv, w_ih, w_hh, b_ih, b_hh, h_ptr, V);
    }

    // 5) decoder
    decoder_kernel<<<V, 64>>>(h_ptr, w_d1, b_d1, w_d2, b_d2, out);
}

// round 5
// speedup vs baseline: 1.2369x; 1.2369x over previous
#include <cuda_runtime.h>
#include <cuda_bf16.h>
#include <math.h>
#include <stdint.h>

#define V_N 20000
#define E_N 100000
#define NODE_IN 128
#define EDGE_IN 128
#define HF 64
#define EDGE_HID 128
#define OUTF 64
#define STEPS 9

// ---------------- scratch (device globals; no allocations allowed) ----------
__device__ float g_h[V_N * HF];                    // node state (h == hidden)
__device__ float g_We[(size_t)E_N * HF * HF];      // per-edge 64x64 matrices (1.64 GB)
__device__ float g_agg[V_N * HF];                  // scatter accumulator
// split-bf16 operands
__device__ __nv_bfloat16 g_efh[E_N * EDGE_IN], g_efl[E_N * EDGE_IN];
__device__ __nv_bfloat16 g_w1h[EDGE_HID * EDGE_IN], g_w1l[EDGE_HID * EDGE_IN];
__device__ __nv_bfloat16 g_w2h[HF * HF * EDGE_HID], g_w2l[HF * HF * EDGE_HID];
__device__ __nv_bfloat16 g_rh[E_N * EDGE_HID], g_rl[E_N * EDGE_HID];

// ---------------- fp32 -> (hi, lo) bf16 split --------------------------------
__global__ void split_kernel(const float* __restrict__ x,
                             __nv_bfloat16* __restrict__ hi,
                             __nv_bfloat16* __restrict__ lo, int n) {
    int i = blockIdx.x * 256 + threadIdx.x;
    if (i < n) {
        float v = x[i];
        __nv_bfloat16 h = __float2bfloat16(v);
        hi[i] = h;
        lo[i] = __float2bfloat16(v - __bfloat162float(h));
    }
}

// ---------------- split-bf16 tensor-core GEMM --------------------------------
// C(MxN) = A(MxK) @ W(NxK)^T + bias, via 3-pass bf16 mma (hi*hi + lo*hi + hi*lo)
// EPI==0: write fp32 C.  EPI==1: relu then write split bf16 (Chi, Clo).
#define BM 128
#define BN 128
#define BKG 32
#define SPAD 8

#define MMA_BF16(c, a, b)                                                      \
    asm volatile(                                                              \
        "mma.sync.aligned.m16n8k16.row.col.f32.bf16.bf16.f32 "                 \
        "{%0,%1,%2,%3}, {%4,%5,%6,%7}, {%8,%9}, {%0,%1,%2,%3};"                \
        : "+f"(c[0]), "+f"(c[1]), "+f"(c[2]), "+f"(c[3])                       \
        : "r"(a[0]), "r"(a[1]), "r"(a[2]), "r"(a[3]), "r"(b[0]), "r"(b[1]))

template <int EPI>
__global__ void __launch_bounds__(256)
mma_gemm(const __nv_bfloat16* __restrict__ Ahi, const __nv_bfloat16* __restrict__ Alo,
         const __nv_bfloat16* __restrict__ Whi, const __nv_bfloat16* __restrict__ Wlo,
         const float* __restrict__ bias,
         float* __restrict__ Cf,
         __nv_bfloat16* __restrict__ Chi, __nv_bfloat16* __restrict__ Clo,
         int M, int N, int K) {
    __shared__ __nv_bfloat16 sAh[BM][BKG + SPAD], sAl[BM][BKG + SPAD];
    __shared__ __nv_bfloat16 sBh[BN][BKG + SPAD], sBl[BN][BKG + SPAD];

    const int tid = threadIdx.x;
    const int m0 = blockIdx.y * BM;
    const int n0 = blockIdx.x * BN;
    const int warp = tid >> 5, lane = tid & 31;
    const int wm = (warp & 1) * 64;   // warp row offset in tile
    const int wn = (warp >> 1) * 32;  // warp col offset in tile
    const int g = lane >> 2, t = lane & 3;

    float c[4][4][4];
#pragma unroll
    for (int mt = 0; mt < 4; mt++)
#pragma unroll
        for (int nt = 0; nt < 4; nt++)
#pragma unroll
            for (int i = 0; i < 4; i++) c[mt][nt][i] = 0.f;

    const int lr = tid >> 2;          // 0..63
    const int lc = (tid & 3) * 8;     // 0,8,16,24

    for (int k0 = 0; k0 < K; k0 += BKG) {
#pragma unroll
        for (int rr = lr; rr < BM; rr += 64) {
            int gm = m0 + rr;
            uint4 vh = make_uint4(0, 0, 0, 0), vl = make_uint4(0, 0, 0, 0);
            if (gm < M) {
                vh = *(const uint4*)&Ahi[(size_t)gm * K + k0 + lc];
                vl = *(const uint4*)&Alo[(size_t)gm * K + k0 + lc];
            }
            *(uint4*)&sAh[rr][lc] = vh;
            *(uint4*)&sAl[rr][lc] = vl;
            *(uint4*)&sBh[rr][lc] = *(const uint4*)&Whi[(size_t)(n0 + rr) * K + k0 + lc];
            *(uint4*)&sBl[rr][lc] = *(const uint4*)&Wlo[(size_t)(n0 + rr) * K + k0 + lc];
        }
        __syncthreads();

#pragma unroll
        for (int kk = 0; kk < 2; kk++) {
            const int kb = kk * 16;
            uint32_t ah[4][4], al[4][4], bh[4][2], bl[4][2];
#pragma unroll
            for (int mt = 0; mt < 4; mt++) {
                int row = wm + mt * 16;
                ah[mt][0] = *(const uint32_t*)&sAh[row + g][kb + 2 * t];
                ah[mt][1] = *(const uint32_t*)&sAh[row + g + 8][kb + 2 * t];
                ah[mt][2] = *(const uint32_t*)&sAh[row + g][kb + 2 * t + 8];
                ah[mt][3] = *(const uint32_t*)&sAh[row + g + 8][kb + 2 * t + 8];
                al[mt][0] = *(const uint32_t*)&sAl[row + g][kb + 2 * t];
                al[mt][1] = *(const uint32_t*)&sAl[row + g + 8][kb + 2 * t];
                al[mt][2] = *(const uint32_t*)&sAl[row + g][kb + 2 * t + 8];
                al[mt][3] = *(const uint32_t*)&sAl[row + g + 8][kb + 2 * t + 8];
            }
#pragma unroll
            for (int nt = 0; nt < 4; nt++) {
                int col = wn + nt * 8 + g;
                bh[nt][0] = *(const uint32_t*)&sBh[col][kb + 2 * t];
                bh[nt][1] = *(const uint32_t*)&sBh[col][kb + 2 * t + 8];
                bl[nt][0] = *(const uint32_t*)&sBl[col][kb + 2 * t];
                bl[nt][1] = *(const uint32_t*)&sBl[col][kb + 2 * t + 8];
            }
#pragma unroll
            for (int mt = 0; mt < 4; mt++)
#pragma unroll
                for (int nt = 0; nt < 4; nt++) {
                    MMA_BF16(c[mt][nt], ah[mt], bh[nt]);
                    MMA_BF16(c[mt][nt], al[mt], bh[nt]);
                    MMA_BF16(c[mt][nt], ah[mt], bl[nt]);
                }
        }
        __syncthreads();
    }

    // epilogue
#pragma unroll
    for (int mt = 0; mt < 4; mt++) {
#pragma unroll
        for (int nt = 0; nt < 4; nt++) {
            int mA = m0 + wm + mt * 16 + g;
            int nA = n0 + wn + nt * 8 + 2 * t;
            float bv0 = bias[nA], bv1 = bias[nA + 1];
#pragma unroll
            for (int half = 0; half < 2; half++) {
                int m = mA + half * 8;
                if (m >= M) continue;
                float v0 = c[mt][nt][half * 2 + 0] + bv0;
                float v1 = c[mt][nt][half * 2 + 1] + bv1;
                if (EPI == 0) {
                    Cf[(size_t)m * N + nA] = v0;
                    Cf[(size_t)m * N + nA + 1] = v1;
                } else {
                    v0 = fmaxf(v0, 0.f);
                    v1 = fmaxf(v1, 0.f);
                    __nv_bfloat16 h0 = __float2bfloat16(v0);
                    __nv_bfloat16 h1 = __float2bfloat16(v1);
                    Chi[(size_t)m * N + nA] = h0;
                    Chi[(size_t)m * N + nA + 1] = h1;
                    Clo[(size_t)m * N + nA] = __float2bfloat16(v0 - __bfloat162float(h0));
                    Clo[(size_t)m * N + nA + 1] = __float2bfloat16(v1 - __bfloat162float(h1));
                }
            }
        }
    }
}

// ---------------- project: h = relu(X@w1^T+b1)@w2^T+b2 ----------------------
__global__ void project_kernel(const float* __restrict__ X,
                               const float* __restrict__ w1, const float* __restrict__ b1,
                               const float* __restrict__ w2, const float* __restrict__ b2,
                               float* __restrict__ Hout) {
    __shared__ float xs[NODE_IN];
    __shared__ float hs[HF];
    int v = blockIdx.x;
    int t = threadIdx.x; // 64 threads
    xs[t]      = X[v * NODE_IN + t];
    xs[t + 64] = X[v * NODE_IN + t + 64];
    __syncthreads();
    float acc = b1[t];
#pragma unroll 8
    for (int i = 0; i < NODE_IN; i++) acc += w1[t * NODE_IN + i] * xs[i];
    hs[t] = fmaxf(acc, 0.f);
    __syncthreads();
    float acc2 = b2[t];
#pragma unroll 8
    for (int i = 0; i < HF; i++) acc2 += w2[t * HF + i] * hs[i];
    Hout[v * HF + t] = acc2;
}

// ---------------- per-edge matvec + scatter ---------------------------------
__global__ void msg_kernel(const float* __restrict__ h,
                           const int* __restrict__ src, const int* __restrict__ dst,
                           const float* __restrict__ We,
                           float* __restrict__ agg, int E) {
    int sub = threadIdx.x >> 6;
    int o = threadIdx.x & 63;
    int e = blockIdx.x * 4 + sub;
    __shared__ float hs[4][HF];
    if (e < E) hs[sub][o] = h[src[e] * HF + o];
    __syncthreads();
    if (e >= E) return;
    const float* hp = hs[sub];
    const float* Wp = We + (size_t)e * (HF * HF) + o;
    float acc = 0.f;
#pragma unroll
    for (int i = 0; i < HF; i++) acc += hp[i] * Wp[(size_t)i * HF];
    atomicAdd(&agg[dst[e] * HF + o], acc);
}

// ---------------- GRU cell (in-place state update) --------------------------
__global__ void gru_kernel(const float* __restrict__ agg, const float* __restrict__ b_conv,
                           const float* __restrict__ w_ih, const float* __restrict__ w_hh,
                           const float* __restrict__ b_ih, const float* __restrict__ b_hh,
                           float* __restrict__ hbuf, int V) {
    int n = threadIdx.x >> 6;
    int o = threadIdx.x & 63;
    int v = blockIdx.x * 4 + n;
    __shared__ float xs[4][HF], hh[4][HF];
    if (v < V) {
        xs[n][o] = fmaxf(agg[v * HF + o] + b_conv[o], 0.f);
        hh[n][o] = hbuf[v * HF + o];
    }
    __syncthreads();
    if (v >= V) return;
    float ir = b_ih[o], iz = b_ih[HF + o], in_ = b_ih[2 * HF + o];
    float hr = b_hh[o], hz = b_hh[HF + o], hn = b_hh[2 * HF + o];
    const float* x = xs[n];
    const float* hv = hh[n];
#pragma unroll 8
    for (int j = 0; j < HF; j++) {
        float xj = x[j], hj = hv[j];
        ir += w_ih[o * HF + j] * xj;
        iz += w_ih[(HF + o) * HF + j] * xj;
        in_ += w_ih[(2 * HF + o) * HF + j] * xj;
        hr += w_hh[o * HF + j] * hj;
        hz += w_hh[(HF + o) * HF + j] * hj;
        hn += w_hh[(2 * HF + o) * HF + j] * hj;
    }
    float r = 1.f / (1.f + expf(-(ir + hr)));
    float z = 1.f / (1.f + expf(-(iz + hz)));
    float nn = tanhf(in_ + r * hn);
    hbuf[v * HF + o] = (1.f - z) * nn + z * hv[o];
}

// ---------------- decoder ---------------------------------------------------
__global__ void decoder_kernel(const float* __restrict__ hbuf,
                               const float* __restrict__ w1, const float* __restrict__ b1,
                               const float* __restrict__ w2, const float* __restrict__ b2,
                               float* __restrict__ out) {
    __shared__ float hs[HF], mid[HF];
    int v = blockIdx.x;
    int t = threadIdx.x; // 64
    hs[t] = hbuf[v * HF + t];
    __syncthreads();
    float a = b1[t];
#pragma unroll 8
    for (int j = 0; j < HF; j++) a += w1[t * HF + j] * hs[j];
    mid[t] = fmaxf(a, 0.f);
    __syncthreads();
    float a2 = b2[t];
#pragma unroll 8
    for (int j = 0; j < HF; j++) a2 += w2[t * HF + j] * mid[j];
    out[v * OUTF + t] = a2;
}

// ---------------- host launch ------------------------------------------------
extern "C" void kernel_launch(void* const* d_in, const int* in_sizes, int n_in,
                              void* d_out, int out_size) {
    const float* node_feats = (const float*)d_in[0];
    const float* edge_feats = (const float*)d_in[1];
    const int* src = (const int*)d_in[2];
    const int* dst = (const int*)d_in[3];
    const float* w_p1 = (const float*)d_in[4];
    const float* b_p1 = (const float*)d_in[5];
    const float* w_p2 = (const float*)d_in[6];
    const float* b_p2 = (const float*)d_in[7];
    const float* w_e1 = (const float*)d_in[8];
    const float* b_e1 = (const float*)d_in[9];
    const float* w_e2 = (const float*)d_in[10];
    const float* b_e2 = (const float*)d_in[11];
    const float* b_conv = (const float*)d_in[12];
    const float* w_ih = (const float*)d_in[13];
    const float* w_hh = (const float*)d_in[14];
    const float* b_ih = (const float*)d_in[15];
    const float* b_hh = (const float*)d_in[16];
    const float* w_d1 = (const float*)d_in[17];
    const float* b_d1 = (const float*)d_in[18];
    const float* w_d2 = (const float*)d_in[19];
    const float* b_d2 = (const float*)d_in[20];
    float* out = (float*)d_out;

    const int V = in_sizes[0] / NODE_IN;
    const int E = in_sizes[2];

    float *h_ptr, *We_ptr, *agg_ptr;
    __nv_bfloat16 *efh, *efl, *w1h, *w1l, *w2h, *w2l, *rh, *rl;
    cudaGetSymbolAddress((void**)&h_ptr, g_h);
    cudaGetSymbolAddress((void**)&We_ptr, g_We);
    cudaGetSymbolAddress((void**)&agg_ptr, g_agg);
    cudaGetSymbolAddress((void**)&efh, g_efh);
    cudaGetSymbolAddress((void**)&efl, g_efl);
    cudaGetSymbolAddress((void**)&w1h, g_w1h);
    cudaGetSymbolAddress((void**)&w1l, g_w1l);
    cudaGetSymbolAddress((void**)&w2h, g_w2h);
    cudaGetSymbolAddress((void**)&w2l, g_w2l);
    cudaGetSymbolAddress((void**)&rh, g_rh);
    cudaGetSymbolAddress((void**)&rl, g_rl);

    // 0) split inputs to (hi, lo) bf16
    {
        int n = E * EDGE_IN;
        split_kernel<<<(n + 255) / 256, 256>>>(edge_feats, efh, efl, n);
        n = EDGE_HID * EDGE_IN;
        split_kernel<<<(n + 255) / 256, 256>>>(w_e1, w1h, w1l, n);
        n = HF * HF * EDGE_HID;
        split_kernel<<<(n + 255) / 256, 256>>>(w_e2, w2h, w2l, n);
    }

    // 1) project node feats
    project_kernel<<<V, 64>>>(node_feats, w_p1, b_p1, w_p2, b_p2, h_ptr);

    // 2) edge network layer 1: r = relu(edge @ w_e1^T + b_e1) -> split bf16
    {
        dim3 grid(EDGE_HID / BN, (E + BM - 1) / BM);
        mma_gemm<1><<<grid, 256>>>(efh, efl, w1h, w1l, b_e1,
                                   nullptr, rh, rl, E, EDGE_HID, EDGE_IN);
    }
    // 3) edge network layer 2: We = r @ w_e2^T + b_e2 (fp32, once)
    {
        dim3 grid((HF * HF) / BN, (E + BM - 1) / BM);
        mma_gemm<0><<<grid, 256>>>(rh, rl, w2h, w2l, b_e2,
                                   We_ptr, nullptr, nullptr, E, HF * HF, EDGE_HID);
    }

    // 4) message passing loop
    for (int s = 0; s < STEPS; s++) {
        cudaMemsetAsync(agg_ptr, 0, (size_t)V * HF * sizeof(float));
        msg_kernel<<<(E + 3) / 4, 256>>>(h_ptr, src, dst, We_ptr, agg_ptr, E);
        gru_kernel<<<(V + 3) / 4, 256>>>(agg_ptr, b_conv, w_ih, w_hh, b_ih, b_hh, h_ptr, V);
    }

    // 5) decoder
    decoder_kernel<<<V, 64>>>(h_ptr, w_d1, b_d1, w_d2, b_d2, out);
}

// round 9
// speedup vs baseline: 5.4822x; 4.4322x over previous
#include <cuda_runtime.h>
#include <cuda_bf16.h>
#include <math.h>
#include <stdint.h>

#define V_N 20000
#define E_N 100000
#define NODE_IN 128
#define EDGE_IN 128
#define HF 64
#define EDGE_HID 128
#define OUTF 64
#define STEPS 9

// ---------------- scratch (device globals; no allocations allowed) ----------
__device__ float g_h[V_N * HF];                    // node state (h == hidden)
__device__ float g_We[(size_t)E_N * HF * HF];      // per-edge 64x64 matrices (1.64 GB)
__device__ float g_agg[V_N * HF];                  // scatter accumulator
__device__ float g_gi[V_N * 3 * HF];               // GRU input gates  (V x 192)
__device__ float g_gh[V_N * 3 * HF];               // GRU hidden gates (V x 192)

// split-bf16 operand buffers (edge path)
__device__ __nv_bfloat16 g_efh[E_N * EDGE_IN], g_efl[E_N * EDGE_IN];
__device__ __nv_bfloat16 g_rh[E_N * EDGE_HID], g_rl[E_N * EDGE_HID];
// split-bf16 operand buffers (node path, reused across phases)
__device__ __nv_bfloat16 g_nh[V_N * NODE_IN], g_nl[V_N * NODE_IN];
__device__ __nv_bfloat16 g_ph[V_N * HF], g_pl[V_N * HF];
// split weights
__device__ __nv_bfloat16 g_w1h[EDGE_HID * EDGE_IN], g_w1l[EDGE_HID * EDGE_IN];
__device__ __nv_bfloat16 g_w2h[HF * HF * EDGE_HID], g_w2l[HF * HF * EDGE_HID];
__device__ __nv_bfloat16 g_wp1h[HF * NODE_IN], g_wp1l[HF * NODE_IN];
__device__ __nv_bfloat16 g_wp2h[HF * HF], g_wp2l[HF * HF];
__device__ __nv_bfloat16 g_wihh[3 * HF * HF], g_wihl[3 * HF * HF];
__device__ __nv_bfloat16 g_whhh[3 * HF * HF], g_whhl[3 * HF * HF];
__device__ __nv_bfloat16 g_wd1h[HF * HF], g_wd1l[HF * HF];
__device__ __nv_bfloat16 g_wd2h[OUTF * HF], g_wd2l[OUTF * HF];

// ---------------- fp32 -> (hi, lo) bf16 split --------------------------------
__global__ void split_kernel(const float* __restrict__ x,
                             __nv_bfloat16* __restrict__ hi,
                             __nv_bfloat16* __restrict__ lo, int n) {
    int i = blockIdx.x * 256 + threadIdx.x;
    if (i < n) {
        float v = x[i];
        __nv_bfloat16 h = __float2bfloat16(v);
        hi[i] = h;
        lo[i] = __float2bfloat16(v - __bfloat162float(h));
    }
}

// ---------------- split-bf16 tensor-core GEMM --------------------------------
// C(MxN) = A(MxK) @ W(NxK)^T + bias, via 3-pass bf16 mma (hi*hi + lo*hi + hi*lo)
// EPI==0: write fp32 C.  EPI==1: relu then write split bf16 (Chi, Clo).
// Handles N not a multiple of BN (tiles zero-padded, stores guarded).
#define BM 128
#define BN 128
#define BKG 32
#define SPAD 8

#define MMA_BF16(c, a, b)                                                      \
    asm volatile(                                                              \
        "mma.sync.aligned.m16n8k16.row.col.f32.bf16.bf16.f32 "                 \
        "{%0,%1,%2,%3}, {%4,%5,%6,%7}, {%8,%9}, {%0,%1,%2,%3};"                \
        : "+f"(c[0]), "+f"(c[1]), "+f"(c[2]), "+f"(c[3])                       \
        : "r"(a[0]), "r"(a[1]), "r"(a[2]), "r"(a[3]), "r"(b[0]), "r"(b[1]))

template <int EPI>
__global__ void __launch_bounds__(256)
mma_gemm(const __nv_bfloat16* __restrict__ Ahi, const __nv_bfloat16* __restrict__ Alo,
         const __nv_bfloat16* __restrict__ Whi, const __nv_bfloat16* __restrict__ Wlo,
         const float* __restrict__ bias,
         float* __restrict__ Cf,
         __nv_bfloat16* __restrict__ Chi, __nv_bfloat16* __restrict__ Clo,
         int M, int N, int K) {
    __shared__ __nv_bfloat16 sAh[BM][BKG + SPAD], sAl[BM][BKG + SPAD];
    __shared__ __nv_bfloat16 sBh[BN][BKG + SPAD], sBl[BN][BKG + SPAD];

    const int tid = threadIdx.x;
    const int m0 = blockIdx.y * BM;
    const int n0 = blockIdx.x * BN;
    const int warp = tid >> 5, lane = tid & 31;
    const int wm = (warp & 1) * 64;   // warp row offset in tile
    const int wn = (warp >> 1) * 32;  // warp col offset in tile
    const int g = lane >> 2, t = lane & 3;

    float c[4][4][4];
#pragma unroll
    for (int mt = 0; mt < 4; mt++)
#pragma unroll
        for (int nt = 0; nt < 4; nt++)
#pragma unroll
            for (int i = 0; i < 4; i++) c[mt][nt][i] = 0.f;

    const int lr = tid >> 2;          // 0..63
    const int lc = (tid & 3) * 8;     // 0,8,16,24

    for (int k0 = 0; k0 < K; k0 += BKG) {
#pragma unroll
        for (int rr = lr; rr < BM; rr += 64) {
            int gm = m0 + rr;
            uint4 vh = make_uint4(0, 0, 0, 0), vl = make_uint4(0, 0, 0, 0);
            if (gm < M) {
                vh = *(const uint4*)&Ahi[(size_t)gm * K + k0 + lc];
                vl = *(const uint4*)&Alo[(size_t)gm * K + k0 + lc];
            }
            *(uint4*)&sAh[rr][lc] = vh;
            *(uint4*)&sAl[rr][lc] = vl;
            int gn = n0 + rr;
            uint4 wh = make_uint4(0, 0, 0, 0), wl = make_uint4(0, 0, 0, 0);
            if (gn < N) {
                wh = *(const uint4*)&Whi[(size_t)gn * K + k0 + lc];
                wl = *(const uint4*)&Wlo[(size_t)gn * K + k0 + lc];
            }
            *(uint4*)&sBh[rr][lc] = wh;
            *(uint4*)&sBl[rr][lc] = wl;
        }
        __syncthreads();

#pragma unroll
        for (int kk = 0; kk < 2; kk++) {
            const int kb = kk * 16;
            uint32_t ah[4][4], al[4][4], bh[4][2], bl[4][2];
#pragma unroll
            for (int mt = 0; mt < 4; mt++) {
                int row = wm + mt * 16;
                ah[mt][0] = *(const uint32_t*)&sAh[row + g][kb + 2 * t];
                ah[mt][1] = *(const uint32_t*)&sAh[row + g + 8][kb + 2 * t];
                ah[mt][2] = *(const uint32_t*)&sAh[row + g][kb + 2 * t + 8];
                ah[mt][3] = *(const uint32_t*)&sAh[row + g + 8][kb + 2 * t + 8];
                al[mt][0] = *(const uint32_t*)&sAl[row + g][kb + 2 * t];
                al[mt][1] = *(const uint32_t*)&sAl[row + g + 8][kb + 2 * t];
                al[mt][2] = *(const uint32_t*)&sAl[row + g][kb + 2 * t + 8];
                al[mt][3] = *(const uint32_t*)&sAl[row + g + 8][kb + 2 * t + 8];
            }
#pragma unroll
            for (int nt = 0; nt < 4; nt++) {
                int col = wn + nt * 8 + g;
                bh[nt][0] = *(const uint32_t*)&sBh[col][kb + 2 * t];
                bh[nt][1] = *(const uint32_t*)&sBh[col][kb + 2 * t + 8];
                bl[nt][0] = *(const uint32_t*)&sBl[col][kb + 2 * t];
                bl[nt][1] = *(const uint32_t*)&sBl[col][kb + 2 * t + 8];
            }
#pragma unroll
            for (int mt = 0; mt < 4; mt++)
#pragma unroll
                for (int nt = 0; nt < 4; nt++) {
                    MMA_BF16(c[mt][nt], ah[mt], bh[nt]);
                    MMA_BF16(c[mt][nt], al[mt], bh[nt]);
                    MMA_BF16(c[mt][nt], ah[mt], bl[nt]);
                }
        }
        __syncthreads();
    }

    // epilogue
#pragma unroll
    for (int mt = 0; mt < 4; mt++) {
#pragma unroll
        for (int nt = 0; nt < 4; nt++) {
            int mA = m0 + wm + mt * 16 + g;
            int nA = n0 + wn + nt * 8 + 2 * t;
            if (nA >= N) continue;
            float bv0 = bias[nA];
            float bv1 = (nA + 1 < N) ? bias[nA + 1] : 0.f;
#pragma unroll
            for (int half = 0; half < 2; half++) {
                int m = mA + half * 8;
                if (m >= M) continue;
                float v0 = c[mt][nt][half * 2 + 0] + bv0;
                float v1 = c[mt][nt][half * 2 + 1] + bv1;
                if (EPI == 0) {
                    Cf[(size_t)m * N + nA] = v0;
                    if (nA + 1 < N) Cf[(size_t)m * N + nA + 1] = v1;
                } else {
                    v0 = fmaxf(v0, 0.f);
                    v1 = fmaxf(v1, 0.f);
                    __nv_bfloat16 h0 = __float2bfloat16(v0);
                    __nv_bfloat16 h1 = __float2bfloat16(v1);
                    Chi[(size_t)m * N + nA] = h0;
                    Clo[(size_t)m * N + nA] = __float2bfloat16(v0 - __bfloat162float(h0));
                    if (nA + 1 < N) {
                        Chi[(size_t)m * N + nA + 1] = h1;
                        Clo[(size_t)m * N + nA + 1] = __float2bfloat16(v1 - __bfloat162float(h1));
                    }
                }
            }
        }
    }
}

// ---------------- per-edge matvec + scatter ---------------------------------
__global__ void msg_kernel(const float* __restrict__ h,
                           const int* __restrict__ src, const int* __restrict__ dst,
                           const float* __restrict__ We,
                           float* __restrict__ agg, int E) {
    int sub = threadIdx.x >> 6;
    int o = threadIdx.x & 63;
    int e = blockIdx.x * 4 + sub;
    __shared__ float hs[4][HF];
    if (e < E) hs[sub][o] = h[src[e] * HF + o];
    __syncthreads();
    if (e >= E) return;
    const float* hp = hs[sub];
    const float* Wp = We + (size_t)e * (HF * HF) + o;
    float acc = 0.f;
#pragma unroll
    for (int i = 0; i < HF; i++) acc += hp[i] * Wp[(size_t)i * HF];
    atomicAdd(&agg[dst[e] * HF + o], acc);
}

// ---------------- GRU prep: x = relu(agg + b_conv); split x and hidden ------
__global__ void prep_kernel(const float* __restrict__ agg, const float* __restrict__ b_conv,
                            const float* __restrict__ hbuf,
                            __nv_bfloat16* __restrict__ xh, __nv_bfloat16* __restrict__ xl,
                            __nv_bfloat16* __restrict__ hh, __nv_bfloat16* __restrict__ hl,
                            int n) {
    int i = blockIdx.x * 256 + threadIdx.x;
    if (i >= n) return;
    int o = i & (HF - 1);
    float x = fmaxf(agg[i] + b_conv[o], 0.f);
    __nv_bfloat16 a = __float2bfloat16(x);
    xh[i] = a;
    xl[i] = __float2bfloat16(x - __bfloat162float(a));
    float hv = hbuf[i];
    __nv_bfloat16 b = __float2bfloat16(hv);
    hh[i] = b;
    hl[i] = __float2bfloat16(hv - __bfloat162float(b));
}

// ---------------- GRU gates (elementwise) ------------------------------------
__global__ void gate_kernel(const float* __restrict__ gi, const float* __restrict__ gh,
                            float* __restrict__ hbuf, int n) {
    int i = blockIdx.x * 256 + threadIdx.x;
    if (i >= n) return;
    int v = i >> 6, o = i & (HF - 1);
    const float* giv = gi + v * 3 * HF;
    const float* ghv = gh + v * 3 * HF;
    float ir = giv[o], iz = giv[HF + o], in_ = giv[2 * HF + o];
    float hr = ghv[o], hz = ghv[HF + o], hn = ghv[2 * HF + o];
    float hv = hbuf[i];
    float r = 1.f / (1.f + expf(-(ir + hr)));
    float z = 1.f / (1.f + expf(-(iz + hz)));
    float nn = tanhf(in_ + r * hn);
    hbuf[i] = (1.f - z) * nn + z * hv;
}

// ---------------- host launch ------------------------------------------------
extern "C" void kernel_launch(void* const* d_in, const int* in_sizes, int n_in,
                              void* d_out, int out_size) {
    const float* node_feats = (const float*)d_in[0];
    const float* edge_feats = (const float*)d_in[1];
    const int* src = (const int*)d_in[2];
    const int* dst = (const int*)d_in[3];
    const float* w_p1 = (const float*)d_in[4];
    const float* b_p1 = (const float*)d_in[5];
    const float* w_p2 = (const float*)d_in[6];
    const float* b_p2 = (const float*)d_in[7];
    const float* w_e1 = (const float*)d_in[8];
    const float* b_e1 = (const float*)d_in[9];
    const float* w_e2 = (const float*)d_in[10];
    const float* b_e2 = (const float*)d_in[11];
    const float* b_conv = (const float*)d_in[12];
    const float* w_ih = (const float*)d_in[13];
    const float* w_hh = (const float*)d_in[14];
    const float* b_ih = (const float*)d_in[15];
    const float* b_hh = (const float*)d_in[16];
    const float* w_d1 = (const float*)d_in[17];
    const float* b_d1 = (const float*)d_in[18];
    const float* w_d2 = (const float*)d_in[19];
    const float* b_d2 = (const float*)d_in[20];
    float* out = (float*)d_out;

    const int V = in_sizes[0] / NODE_IN;
    const int E = in_sizes[2];

    float *h_ptr, *We_ptr, *agg_ptr, *gi_ptr, *gh_ptr;
    __nv_bfloat16 *efh, *efl, *rh, *rl, *nh, *nl, *ph, *pl;
    __nv_bfloat16 *w1h, *w1l, *w2h, *w2l, *wp1h, *wp1l, *wp2h, *wp2l;
    __nv_bfloat16 *wihh, *wihl, *whhh, *whhl, *wd1h, *wd1l, *wd2h, *wd2l;
    cudaGetSymbolAddress((void**)&h_ptr, g_h);
    cudaGetSymbolAddress((void**)&We_ptr, g_We);
    cudaGetSymbolAddress((void**)&agg_ptr, g_agg);
    cudaGetSymbolAddress((void**)&gi_ptr, g_gi);
    cudaGetSymbolAddress((void**)&gh_ptr, g_gh);
    cudaGetSymbolAddress((void**)&efh, g_efh);
    cudaGetSymbolAddress((void**)&efl, g_efl);
    cudaGetSymbolAddress((void**)&rh, g_rh);
    cudaGetSymbolAddress((void**)&rl, g_rl);
    cudaGetSymbolAddress((void**)&nh, g_nh);
    cudaGetSymbolAddress((void**)&nl, g_nl);
    cudaGetSymbolAddress((void**)&ph, g_ph);
    cudaGetSymbolAddress((void**)&pl, g_pl);
    cudaGetSymbolAddress((void**)&w1h, g_w1h);
    cudaGetSymbolAddress((void**)&w1l, g_w1l);
    cudaGetSymbolAddress((void**)&w2h, g_w2h);
    cudaGetSymbolAddress((void**)&w2l, g_w2l);
    cudaGetSymbolAddress((void**)&wp1h, g_wp1h);
    cudaGetSymbolAddress((void**)&wp1l, g_wp1l);
    cudaGetSymbolAddress((void**)&wp2h, g_wp2h);
    cudaGetSymbolAddress((void**)&wp2l, g_wp2l);
    cudaGetSymbolAddress((void**)&wihh, g_wihh);
    cudaGetSymbolAddress((void**)&wihl, g_wihl);
    cudaGetSymbolAddress((void**)&whhh, g_whhh);
    cudaGetSymbolAddress((void**)&whhl, g_whhl);
    cudaGetSymbolAddress((void**)&wd1h, g_wd1h);
    cudaGetSymbolAddress((void**)&wd1l, g_wd1l);
    cudaGetSymbolAddress((void**)&wd2h, g_wd2h);
    cudaGetSymbolAddress((void**)&wd2l, g_wd2l);

    // 0) split inputs / weights to (hi, lo) bf16
    {
        int n;
        n = E * EDGE_IN;        split_kernel<<<(n + 255) / 256, 256>>>(edge_feats, efh, efl, n);
        n = V * NODE_IN;        split_kernel<<<(n + 255) / 256, 256>>>(node_feats, nh, nl, n);
        n = EDGE_HID * EDGE_IN; split_kernel<<<(n + 255) / 256, 256>>>(w_e1, w1h, w1l, n);
        n = HF * HF * EDGE_HID; split_kernel<<<(n + 255) / 256, 256>>>(w_e2, w2h, w2l, n);
        n = HF * NODE_IN;       split_kernel<<<(n + 255) / 256, 256>>>(w_p1, wp1h, wp1l, n);
        n = HF * HF;            split_kernel<<<(n + 255) / 256, 256>>>(w_p2, wp2h, wp2l, n);
        n = 3 * HF * HF;        split_kernel<<<(n + 255) / 256, 256>>>(w_ih, wihh, wihl, n);
        n = 3 * HF * HF;        split_kernel<<<(n + 255) / 256, 256>>>(w_hh, whhh, whhl, n);
        n = HF * HF;            split_kernel<<<(n + 255) / 256, 256>>>(w_d1, wd1h, wd1l, n);
        n = OUTF * HF;          split_kernel<<<(n + 255) / 256, 256>>>(w_d2, wd2h, wd2l, n);
    }

    const int mb_v = (V + BM - 1) / BM;
    const int mb_e = (E + BM - 1) / BM;

    // 1) project node feats: relu(X@w_p1^T+b_p1) @ w_p2^T + b_p2 -> g_h
    mma_gemm<1><<<dim3(1, mb_v), 256>>>(nh, nl, wp1h, wp1l, b_p1,
                                        nullptr, ph, pl, V, HF, NODE_IN);
    mma_gemm<0><<<dim3(1, mb_v), 256>>>(ph, pl, wp2h, wp2l, b_p2,
                                        h_ptr, nullptr, nullptr, V, HF, HF);

    // 2) edge network layer 1: r = relu(edge @ w_e1^T + b_e1) -> split bf16
    mma_gemm<1><<<dim3(EDGE_HID / BN, mb_e), 256>>>(efh, efl, w1h, w1l, b_e1,
                                                    nullptr, rh, rl, E, EDGE_HID, EDGE_IN);
    // 3) edge network layer 2: We = r @ w_e2^T + b_e2 (fp32, once)
    mma_gemm<0><<<dim3((HF * HF) / BN, mb_e), 256>>>(rh, rl, w2h, w2l, b_e2,
                                                     We_ptr, nullptr, nullptr, E, HF * HF, EDGE_HID);

    // 4) message passing loop
    const int nV = V * HF;
    for (int s = 0; s < STEPS; s++) {
        cudaMemsetAsync(agg_ptr, 0, (size_t)nV * sizeof(float));
        msg_kernel<<<(E + 3) / 4, 256>>>(h_ptr, src, dst, We_ptr, agg_ptr, E);
        prep_kernel<<<(nV + 255) / 256, 256>>>(agg_ptr, b_conv, h_ptr, nh, nl, ph, pl, nV);
        mma_gemm<0><<<dim3(2, mb_v), 256>>>(nh, nl, wihh, wihl, b_ih,
                                            gi_ptr, nullptr, nullptr, V, 3 * HF, HF);
        mma_gemm<0><<<dim3(2, mb_v), 256>>>(ph, pl, whhh, whhl, b_hh,
                                            gh_ptr, nullptr, nullptr, V, 3 * HF, HF);
        gate_kernel<<<(nV + 255) / 256, 256>>>(gi_ptr, gh_ptr, h_ptr, nV);
    }

    // 5) decoder: relu(h@w_d1^T+b_d1) @ w_d2^T + b_d2 -> out
    split_kernel<<<(nV + 255) / 256, 256>>>(h_ptr, nh, nl, nV);
    mma_gemm<1><<<dim3(1, mb_v), 256>>>(nh, nl, wd1h, wd1l, b_d1,
                                        nullptr, ph, pl, V, HF, HF);
    mma_gemm<0><<<dim3(1, mb_v), 256>>>(ph, pl, wd2h, wd2l, b_d2,
                                        out, nullptr, nullptr, V, OUTF, HF);
}

// round 13
// speedup vs baseline: 6.0324x; 1.1004x over previous
#include <cuda_runtime.h>
#include <cuda_bf16.h>
#include <cuda_fp16.h>
#include <math.h>
#include <stdint.h>

#define V_N 20000
#define E_N 100000
#define NODE_IN 128
#define EDGE_IN 128
#define HF 64
#define EDGE_HID 128
#define OUTF 64
#define STEPS 9

// ---------------- scratch (device globals; no allocations allowed) ----------
__device__ float g_h[V_N * HF];                    // node state fp32
__device__ __half g_We[(size_t)E_N * HF * HF];     // per-edge 64x64 matrices (fp16, 819 MB)
__device__ float g_agg[V_N * HF];                  // scatter accumulator
__device__ float g_gates[V_N * 4 * HF];            // fused GRU gates (V x 256)

// split-bf16 operand buffers
__device__ __nv_bfloat16 g_efh[E_N * EDGE_IN], g_efl[E_N * EDGE_IN];
__device__ __nv_bfloat16 g_rh[E_N * EDGE_HID], g_rl[E_N * EDGE_HID];
__device__ __nv_bfloat16 g_nh[V_N * 128], g_nl[V_N * 128];   // [x|h] per node (also node feats)
__device__ __nv_bfloat16 g_ph[V_N * HF], g_pl[V_N * HF];
// split weights
__device__ __nv_bfloat16 g_w1h[EDGE_HID * EDGE_IN], g_w1l[EDGE_HID * EDGE_IN];
__device__ __nv_bfloat16 g_w2h[HF * HF * EDGE_HID], g_w2l[HF * HF * EDGE_HID];
__device__ __nv_bfloat16 g_wp1h[HF * NODE_IN], g_wp1l[HF * NODE_IN];
__device__ __nv_bfloat16 g_wp2h[HF * HF], g_wp2l[HF * HF];
__device__ __nv_bfloat16 g_wd1h[HF * HF], g_wd1l[HF * HF];
__device__ __nv_bfloat16 g_wd2h[OUTF * HF], g_wd2l[OUTF * HF];
// fused GRU weight: W' (256 x 128) and bias (256)
__device__ float g_wgf[256 * 128];
__device__ float g_bg[256];
__device__ __nv_bfloat16 g_wgh[256 * 128], g_wgl[256 * 128];

// ---------------- fp32 -> (hi, lo) bf16 split --------------------------------
__global__ void split_kernel(const float* __restrict__ x,
                             __nv_bfloat16* __restrict__ hi,
                             __nv_bfloat16* __restrict__ lo, int n) {
    int i = blockIdx.x * 256 + threadIdx.x;
    if (i < n) {
        float v = x[i];
        __nv_bfloat16 h = __float2bfloat16(v);
        hi[i] = h;
        lo[i] = __float2bfloat16(v - __bfloat162float(h));
    }
}

// ---------------- build fused GRU weight W' (256x128) + bias ----------------
// rows 0..127:   [w_ih[j] | w_hh[j]]        bias b_ih[j]+b_hh[j]   (r,z combined)
// rows 128..191: [w_ih[j] | 0]              bias b_ih[j]           (i_n)
// rows 192..255: [0 | w_hh[j-64]]           bias b_hh[j-64]        (h_n)
__global__ void build_gru_w(const float* __restrict__ w_ih, const float* __restrict__ w_hh,
                            const float* __restrict__ b_ih, const float* __restrict__ b_hh,
                            float* __restrict__ W, float* __restrict__ B) {
    int i = blockIdx.x * 256 + threadIdx.x;
    if (i >= 256 * 128) return;
    int j = i >> 7, k = i & 127;
    float v = 0.f;
    if (j < 128) {
        v = (k < HF) ? w_ih[j * HF + k] : w_hh[j * HF + (k - HF)];
    } else if (j < 192) {
        if (k < HF) v = w_ih[j * HF + k];
    } else {
        if (k >= HF) v = w_hh[(j - HF) * HF + (k - HF)];
    }
    W[i] = v;
    if (k == 0) {
        float b;
        if (j < 128) b = b_ih[j] + b_hh[j];
        else if (j < 192) b = b_ih[j];
        else b = b_hh[j - HF];
        B[j] = b;
    }
}

// ---------------- split-bf16 tensor-core GEMM --------------------------------
// C(MxN) = A(MxK) @ W(NxK)^T + bias (3-pass split-bf16 mma, fp32 accum)
// EPI==0: fp32 out. EPI==1: relu -> split bf16 out. EPI==2: fp16 out.
#define BM 128
#define BN 128
#define BKG 32
#define SPAD 8

#define MMA_BF16(c, a, b)                                                      \
    asm volatile(                                                              \
        "mma.sync.aligned.m16n8k16.row.col.f32.bf16.bf16.f32 "                 \
        "{%0,%1,%2,%3}, {%4,%5,%6,%7}, {%8,%9}, {%0,%1,%2,%3};"                \
        : "+f"(c[0]), "+f"(c[1]), "+f"(c[2]), "+f"(c[3])                       \
        : "r"(a[0]), "r"(a[1]), "r"(a[2]), "r"(a[3]), "r"(b[0]), "r"(b[1]))

template <int EPI>
__global__ void __launch_bounds__(256)
mma_gemm(const __nv_bfloat16* __restrict__ Ahi, const __nv_bfloat16* __restrict__ Alo,
         const __nv_bfloat16* __restrict__ Whi, const __nv_bfloat16* __restrict__ Wlo,
         const float* __restrict__ bias,
         float* __restrict__ Cf,
         __nv_bfloat16* __restrict__ Chi, __nv_bfloat16* __restrict__ Clo,
         __half* __restrict__ Ch16,
         int M, int N, int K) {
    __shared__ __nv_bfloat16 sAh[BM][BKG + SPAD], sAl[BM][BKG + SPAD];
    __shared__ __nv_bfloat16 sBh[BN][BKG + SPAD], sBl[BN][BKG + SPAD];

    const int tid = threadIdx.x;
    const int m0 = blockIdx.y * BM;
    const int n0 = blockIdx.x * BN;
    const int warp = tid >> 5, lane = tid & 31;
    const int wm = (warp & 1) * 64;
    const int wn = (warp >> 1) * 32;
    const int g = lane >> 2, t = lane & 3;

    float c[4][4][4];
#pragma unroll
    for (int mt = 0; mt < 4; mt++)
#pragma unroll
        for (int nt = 0; nt < 4; nt++)
#pragma unroll
            for (int i = 0; i < 4; i++) c[mt][nt][i] = 0.f;

    const int lr = tid >> 2;
    const int lc = (tid & 3) * 8;

    for (int k0 = 0; k0 < K; k0 += BKG) {
#pragma unroll
        for (int rr = lr; rr < BM; rr += 64) {
            int gm = m0 + rr;
            uint4 vh = make_uint4(0, 0, 0, 0), vl = make_uint4(0, 0, 0, 0);
            if (gm < M) {
                vh = *(const uint4*)&Ahi[(size_t)gm * K + k0 + lc];
                vl = *(const uint4*)&Alo[(size_t)gm * K + k0 + lc];
            }
            *(uint4*)&sAh[rr][lc] = vh;
            *(uint4*)&sAl[rr][lc] = vl;
            int gn = n0 + rr;
            uint4 wh = make_uint4(0, 0, 0, 0), wl = make_uint4(0, 0, 0, 0);
            if (gn < N) {
                wh = *(const uint4*)&Whi[(size_t)gn * K + k0 + lc];
                wl = *(const uint4*)&Wlo[(size_t)gn * K + k0 + lc];
            }
            *(uint4*)&sBh[rr][lc] = wh;
            *(uint4*)&sBl[rr][lc] = wl;
        }
        __syncthreads();

#pragma unroll
        for (int kk = 0; kk < 2; kk++) {
            const int kb = kk * 16;
            uint32_t ah[4][4], al[4][4], bh[4][2], bl[4][2];
#pragma unroll
            for (int mt = 0; mt < 4; mt++) {
                int row = wm + mt * 16;
                ah[mt][0] = *(const uint32_t*)&sAh[row + g][kb + 2 * t];
                ah[mt][1] = *(const uint32_t*)&sAh[row + g + 8][kb + 2 * t];
                ah[mt][2] = *(const uint32_t*)&sAh[row + g][kb + 2 * t + 8];
                ah[mt][3] = *(const uint32_t*)&sAh[row + g + 8][kb + 2 * t + 8];
                al[mt][0] = *(const uint32_t*)&sAl[row + g][kb + 2 * t];
                al[mt][1] = *(const uint32_t*)&sAl[row + g + 8][kb + 2 * t];
                al[mt][2] = *(const uint32_t*)&sAl[row + g][kb + 2 * t + 8];
                al[mt][3] = *(const uint32_t*)&sAl[row + g + 8][kb + 2 * t + 8];
            }
#pragma unroll
            for (int nt = 0; nt < 4; nt++) {
                int col = wn + nt * 8 + g;
                bh[nt][0] = *(const uint32_t*)&sBh[col][kb + 2 * t];
                bh[nt][1] = *(const uint32_t*)&sBh[col][kb + 2 * t + 8];
                bl[nt][0] = *(const uint32_t*)&sBl[col][kb + 2 * t];
                bl[nt][1] = *(const uint32_t*)&sBl[col][kb + 2 * t + 8];
            }
#pragma unroll
            for (int mt = 0; mt < 4; mt++)
#pragma unroll
                for (int nt = 0; nt < 4; nt++) {
                    MMA_BF16(c[mt][nt], ah[mt], bh[nt]);
                    MMA_BF16(c[mt][nt], al[mt], bh[nt]);
                    MMA_BF16(c[mt][nt], ah[mt], bl[nt]);
                }
        }
        __syncthreads();
    }

#pragma unroll
    for (int mt = 0; mt < 4; mt++) {
#pragma unroll
        for (int nt = 0; nt < 4; nt++) {
            int mA = m0 + wm + mt * 16 + g;
            int nA = n0 + wn + nt * 8 + 2 * t;
            if (nA >= N) continue;
            float bv0 = bias[nA];
            float bv1 = (nA + 1 < N) ? bias[nA + 1] : 0.f;
#pragma unroll
            for (int half = 0; half < 2; half++) {
                int m = mA + half * 8;
                if (m >= M) continue;
                float v0 = c[mt][nt][half * 2 + 0] + bv0;
                float v1 = c[mt][nt][half * 2 + 1] + bv1;
                if (EPI == 0) {
                    Cf[(size_t)m * N + nA] = v0;
                    if (nA + 1 < N) Cf[(size_t)m * N + nA + 1] = v1;
                } else if (EPI == 2) {
                    Ch16[(size_t)m * N + nA] = __float2half_rn(v0);
                    if (nA + 1 < N) Ch16[(size_t)m * N + nA + 1] = __float2half_rn(v1);
                } else {
                    v0 = fmaxf(v0, 0.f);
                    v1 = fmaxf(v1, 0.f);
                    __nv_bfloat16 h0 = __float2bfloat16(v0);
                    __nv_bfloat16 h1 = __float2bfloat16(v1);
                    Chi[(size_t)m * N + nA] = h0;
                    Clo[(size_t)m * N + nA] = __float2bfloat16(v0 - __bfloat162float(h0));
                    if (nA + 1 < N) {
                        Chi[(size_t)m * N + nA + 1] = h1;
                        Clo[(size_t)m * N + nA + 1] = __float2bfloat16(v1 - __bfloat162float(h1));
                    }
                }
            }
        }
    }
}

// ---------------- per-edge matvec (fp16 We) + scatter ------------------------
__global__ void msg_kernel(const float* __restrict__ h,
                           const int* __restrict__ src, const int* __restrict__ dst,
                           const __half* __restrict__ We,
                           float* __restrict__ agg, int E) {
    int sub = threadIdx.x >> 6;
    int o = threadIdx.x & 63;
    int e = blockIdx.x * 4 + sub;
    __shared__ float hs[4][HF];
    if (e < E) hs[sub][o] = h[src[e] * HF + o];
    __syncthreads();
    if (e >= E) return;
    const float* hp = hs[sub];
    const __half* Wp = We + (size_t)e * (HF * HF) + o;
    float acc = 0.f;
#pragma unroll
    for (int i = 0; i < HF; i++) acc += hp[i] * __half2float(__ldg(&Wp[(size_t)i * HF]));
    atomicAdd(&agg[dst[e] * HF + o], acc);
}

// ---------------- init: h-split into A buffer cols 64..127; zero agg --------
__global__ void init_state(const float* __restrict__ hbuf,
                           __nv_bfloat16* __restrict__ ah, __nv_bfloat16* __restrict__ al,
                           float* __restrict__ agg, int n) {
    int i = blockIdx.x * 256 + threadIdx.x;
    if (i >= n) return;
    int v = i >> 6, o = i & (HF - 1);
    float hv = hbuf[i];
    __nv_bfloat16 b = __float2bfloat16(hv);
    ah[v * 128 + HF + o] = b;
    al[v * 128 + HF + o] = __float2bfloat16(hv - __bfloat162float(b));
    agg[i] = 0.f;
}

// ---------------- prep: x = relu(agg+b_conv) -> split into A cols 0..63 -----
__global__ void prep_x(const float* __restrict__ agg, const float* __restrict__ b_conv,
                       __nv_bfloat16* __restrict__ ah, __nv_bfloat16* __restrict__ al,
                       int n) {
    int i = blockIdx.x * 256 + threadIdx.x;
    if (i >= n) return;
    int v = i >> 6, o = i & (HF - 1);
    float x = fmaxf(agg[i] + b_conv[o], 0.f);
    __nv_bfloat16 a = __float2bfloat16(x);
    ah[v * 128 + o] = a;
    al[v * 128 + o] = __float2bfloat16(x - __bfloat162float(a));
}

// ---------------- gates: GRU update + re-split h + zero agg ------------------
__global__ void gate_kernel(const float* __restrict__ gates,
                            float* __restrict__ hbuf,
                            __nv_bfloat16* __restrict__ ah, __nv_bfloat16* __restrict__ al,
                            float* __restrict__ agg, int n) {
    int i = blockIdx.x * 256 + threadIdx.x;
    if (i >= n) return;
    int v = i >> 6, o = i & (HF - 1);
    const float* gv = gates + (size_t)v * 4 * HF;
    float r = 1.f / (1.f + expf(-gv[o]));
    float z = 1.f / (1.f + expf(-gv[HF + o]));
    float nn = tanhf(gv[2 * HF + o] + r * gv[3 * HF + o]);
    float hv = hbuf[i];
    float h_new = (1.f - z) * nn + z * hv;
    hbuf[i] = h_new;
    __nv_bfloat16 b = __float2bfloat16(h_new);
    ah[v * 128 + HF + o] = b;
    al[v * 128 + HF + o] = __float2bfloat16(h_new - __bfloat162float(b));
    agg[i] = 0.f;
}

// ---------------- host launch ------------------------------------------------
extern "C" void kernel_launch(void* const* d_in, const int* in_sizes, int n_in,
                              void* d_out, int out_size) {
    const float* node_feats = (const float*)d_in[0];
    const float* edge_feats = (const float*)d_in[1];
    const int* src = (const int*)d_in[2];
    const int* dst = (const int*)d_in[3];
    const float* w_p1 = (const float*)d_in[4];
    const float* b_p1 = (const float*)d_in[5];
    const float* w_p2 = (const float*)d_in[6];
    const float* b_p2 = (const float*)d_in[7];
    const float* w_e1 = (const float*)d_in[8];
    const float* b_e1 = (const float*)d_in[9];
    const float* w_e2 = (const float*)d_in[10];
    const float* b_e2 = (const float*)d_in[11];
    const float* b_conv = (const float*)d_in[12];
    const float* w_ih = (const float*)d_in[13];
    const float* w_hh = (const float*)d_in[14];
    const float* b_ih = (const float*)d_in[15];
    const float* b_hh = (const float*)d_in[16];
    const float* w_d1 = (const float*)d_in[17];
    const float* b_d1 = (const float*)d_in[18];
    const float* w_d2 = (const float*)d_in[19];
    const float* b_d2 = (const float*)d_in[20];
    float* out = (float*)d_out;

    const int V = in_sizes[0] / NODE_IN;
    const int E = in_sizes[2];

    float *h_ptr, *agg_ptr, *gates_ptr, *wgf_ptr, *bg_ptr;
    __half* We_ptr;
    __nv_bfloat16 *efh, *efl, *rh, *rl, *nh, *nl, *ph, *pl;
    __nv_bfloat16 *w1h, *w1l, *w2h, *w2l, *wp1h, *wp1l, *wp2h, *wp2l;
    __nv_bfloat16 *wd1h, *wd1l, *wd2h, *wd2l, *wgh, *wgl;
    cudaGetSymbolAddress((void**)&h_ptr, g_h);
    cudaGetSymbolAddress((void**)&We_ptr, g_We);
    cudaGetSymbolAddress((void**)&agg_ptr, g_agg);
    cudaGetSymbolAddress((void**)&gates_ptr, g_gates);
    cudaGetSymbolAddress((void**)&wgf_ptr, g_wgf);
    cudaGetSymbolAddress((void**)&bg_ptr, g_bg);
    cudaGetSymbolAddress((void**)&efh, g_efh);
    cudaGetSymbolAddress((void**)&efl, g_efl);
    cudaGetSymbolAddress((void**)&rh, g_rh);
    cudaGetSymbolAddress((void**)&rl, g_rl);
    cudaGetSymbolAddress((void**)&nh, g_nh);
    cudaGetSymbolAddress((void**)&nl, g_nl);
    cudaGetSymbolAddress((void**)&ph, g_ph);
    cudaGetSymbolAddress((void**)&pl, g_pl);
    cudaGetSymbolAddress((void**)&w1h, g_w1h);
    cudaGetSymbolAddress((void**)&w1l, g_w1l);
    cudaGetSymbolAddress((void**)&w2h, g_w2h);
    cudaGetSymbolAddress((void**)&w2l, g_w2l);
    cudaGetSymbolAddress((void**)&wp1h, g_wp1h);
    cudaGetSymbolAddress((void**)&wp1l, g_wp1l);
    cudaGetSymbolAddress((void**)&wp2h, g_wp2h);
    cudaGetSymbolAddress((void**)&wp2l, g_wp2l);
    cudaGetSymbolAddress((void**)&wd1h, g_wd1h);
    cudaGetSymbolAddress((void**)&wd1l, g_wd1l);
    cudaGetSymbolAddress((void**)&wd2h, g_wd2h);
    cudaGetSymbolAddress((void**)&wd2l, g_wd2l);
    cudaGetSymbolAddress((void**)&wgh, g_wgh);
    cudaGetSymbolAddress((void**)&wgl, g_wgl);

    // 0) split inputs / weights; build fused GRU weight
    {
        int n;
        n = E * EDGE_IN;        split_kernel<<<(n + 255) / 256, 256>>>(edge_feats, efh, efl, n);
        n = V * NODE_IN;        split_kernel<<<(n + 255) / 256, 256>>>(node_feats, nh, nl, n);
        n = EDGE_HID * EDGE_IN; split_kernel<<<(n + 255) / 256, 256>>>(w_e1, w1h, w1l, n);
        n = HF * HF * EDGE_HID; split_kernel<<<(n + 255) / 256, 256>>>(w_e2, w2h, w2l, n);
        n = HF * NODE_IN;       split_kernel<<<(n + 255) / 256, 256>>>(w_p1, wp1h, wp1l, n);
        n = HF * HF;            split_kernel<<<(n + 255) / 256, 256>>>(w_p2, wp2h, wp2l, n);
        n = HF * HF;            split_kernel<<<(n + 255) / 256, 256>>>(w_d1, wd1h, wd1l, n);
        n = OUTF * HF;          split_kernel<<<(n + 255) / 256, 256>>>(w_d2, wd2h, wd2l, n);
        build_gru_w<<<(256 * 128 + 255) / 256, 256>>>(w_ih, w_hh, b_ih, b_hh, wgf_ptr, bg_ptr);
        n = 256 * 128;          split_kernel<<<(n + 255) / 256, 256>>>(wgf_ptr, wgh, wgl, n);
    }

    const int mb_v = (V + BM - 1) / BM;
    const int mb_e = (E + BM - 1) / BM;
    const int nV = V * HF;

    // 1) project node feats -> g_h (fp32)
    mma_gemm<1><<<dim3(1, mb_v), 256>>>(nh, nl, wp1h, wp1l, b_p1,
                                        nullptr, ph, pl, nullptr, V, HF, NODE_IN);
    mma_gemm<0><<<dim3(1, mb_v), 256>>>(ph, pl, wp2h, wp2l, b_p2,
                                        h_ptr, nullptr, nullptr, nullptr, V, HF, HF);

    // 2) edge network -> We (fp16)
    mma_gemm<1><<<dim3(EDGE_HID / BN, mb_e), 256>>>(efh, efl, w1h, w1l, b_e1,
                                                    nullptr, rh, rl, nullptr, E, EDGE_HID, EDGE_IN);
    mma_gemm<2><<<dim3((HF * HF) / BN, mb_e), 256>>>(rh, rl, w2h, w2l, b_e2,
                                                     nullptr, nullptr, nullptr, We_ptr,
                                                     E, HF * HF, EDGE_HID);

    // 3) init fused-A buffer with h, zero agg
    init_state<<<(nV + 255) / 256, 256>>>(h_ptr, nh, nl, agg_ptr, nV);

    // 4) message passing loop
    for (int s = 0; s < STEPS; s++) {
        msg_kernel<<<(E + 3) / 4, 256>>>(h_ptr, src, dst, We_ptr, agg_ptr, E);
        prep_x<<<(nV + 255) / 256, 256>>>(agg_ptr, b_conv, nh, nl, nV);
        mma_gemm<0><<<dim3(2, mb_v), 256>>>(nh, nl, wgh, wgl, bg_ptr,
                                            gates_ptr, nullptr, nullptr, nullptr, V, 4 * HF, 128);
        gate_kernel<<<(nV + 255) / 256, 256>>>(gates_ptr, h_ptr, nh, nl, agg_ptr, nV);
    }

    // 5) decoder
    split_kernel<<<(nV + 255) / 256, 256>>>(h_ptr, ph, pl, nV);
    mma_gemm<1><<<dim3(1, mb_v), 256>>>(ph, pl, wd1h, wd1l, b_d1,
                                        nullptr, rh, rl, nullptr, V, HF, HF);
    mma_gemm<0><<<dim3(1, mb_v), 256>>>(rh, rl, wd2h, wd2l, b_d2,
                                        out, nullptr, nullptr, nullptr, V, OUTF, HF);
}

// round 16
// speedup vs baseline: 9.9179x; 1.6441x over previous
#include <cuda_runtime.h>
#include <cuda_bf16.h>
#include <cuda_fp16.h>
#include <math.h>
#include <stdint.h>

#define V_N 20000
#define E_N 100000
#define NODE_IN 128
#define EDGE_IN 128
#define HF 64
#define EDGE_HID 128
#define OUTF 64
#define STEPS 9

// ---------------- scratch (device globals; no allocations allowed) ----------
__device__ float g_h[V_N * HF];                    // node state fp32
__device__ __half g_We[(size_t)E_N * HF * HF];     // per-edge 64x64 matrices (fp16, 819 MB)
__device__ float g_agg[V_N * HF];                  // scatter accumulator
__device__ float g_gates[V_N * 4 * HF];            // fused GRU gates (V x 256)

// fp16 edge-network operands
__device__ __half g_ef16[E_N * EDGE_IN];
__device__ __half g_r16[E_N * EDGE_HID];
__device__ __half g_w1_16[EDGE_HID * EDGE_IN];
__device__ __half g_w2_16[HF * HF * EDGE_HID];

// split-bf16 operand buffers (node path)
__device__ __nv_bfloat16 g_nh[V_N * 128], g_nl[V_N * 128];   // [x|h] per node (also node feats)
__device__ __nv_bfloat16 g_ph[V_N * HF], g_pl[V_N * HF];
__device__ __nv_bfloat16 g_dh[V_N * HF], g_dl[V_N * HF];
// split weights
__device__ __nv_bfloat16 g_wp1h[HF * NODE_IN], g_wp1l[HF * NODE_IN];
__device__ __nv_bfloat16 g_wp2h[HF * HF], g_wp2l[HF * HF];
__device__ __nv_bfloat16 g_wd1h[HF * HF], g_wd1l[HF * HF];
__device__ __nv_bfloat16 g_wd2h[OUTF * HF], g_wd2l[OUTF * HF];
// fused GRU weight: W' (256 x 128) and bias (256)
__device__ float g_wgf[256 * 128];
__device__ float g_bg[256];
__device__ __nv_bfloat16 g_wgh[256 * 128], g_wgl[256 * 128];

// ---------------- fp32 -> (hi, lo) bf16 split --------------------------------
__global__ void split_kernel(const float* __restrict__ x,
                             __nv_bfloat16* __restrict__ hi,
                             __nv_bfloat16* __restrict__ lo, int n) {
    int i = blockIdx.x * 256 + threadIdx.x;
    if (i < n) {
        float v = x[i];
        __nv_bfloat16 h = __float2bfloat16(v);
        hi[i] = h;
        lo[i] = __float2bfloat16(v - __bfloat162float(h));
    }
}

// ---------------- fp32 -> fp16 convert ---------------------------------------
__global__ void tohalf_kernel(const float* __restrict__ x, __half* __restrict__ y, int n) {
    int i = blockIdx.x * 256 + threadIdx.x;
    if (i < n) y[i] = __float2half_rn(x[i]);
}

// ---------------- build fused GRU weight W' (256x128) + bias ----------------
__global__ void build_gru_w(const float* __restrict__ w_ih, const float* __restrict__ w_hh,
                            const float* __restrict__ b_ih, const float* __restrict__ b_hh,
                            float* __restrict__ W, float* __restrict__ B) {
    int i = blockIdx.x * 256 + threadIdx.x;
    if (i >= 256 * 128) return;
    int j = i >> 7, k = i & 127;
    float v = 0.f;
    if (j < 128) {
        v = (k < HF) ? w_ih[j * HF + k] : w_hh[j * HF + (k - HF)];
    } else if (j < 192) {
        if (k < HF) v = w_ih[j * HF + k];
    } else {
        if (k >= HF) v = w_hh[(j - HF) * HF + (k - HF)];
    }
    W[i] = v;
    if (k == 0) {
        float b;
        if (j < 128) b = b_ih[j] + b_hh[j];
        else if (j < 192) b = b_ih[j];
        else b = b_hh[j - HF];
        B[j] = b;
    }
}

#define BM 128
#define BN 128
#define BKG 32
#define SPAD 8

#define MMA_BF16(c, a, b)                                                      \
    asm volatile(                                                              \
        "mma.sync.aligned.m16n8k16.row.col.f32.bf16.bf16.f32 "                 \
        "{%0,%1,%2,%3}, {%4,%5,%6,%7}, {%8,%9}, {%0,%1,%2,%3};"                \
        : "+f"(c[0]), "+f"(c[1]), "+f"(c[2]), "+f"(c[3])                       \
        : "r"(a[0]), "r"(a[1]), "r"(a[2]), "r"(a[3]), "r"(b[0]), "r"(b[1]))

#define MMA_F16(c, a, b)                                                       \
    asm volatile(                                                              \
        "mma.sync.aligned.m16n8k16.row.col.f32.f16.f16.f32 "                   \
        "{%0,%1,%2,%3}, {%4,%5,%6,%7}, {%8,%9}, {%0,%1,%2,%3};"                \
        : "+f"(c[0]), "+f"(c[1]), "+f"(c[2]), "+f"(c[3])                       \
        : "r"(a[0]), "r"(a[1]), "r"(a[2]), "r"(a[3]), "r"(b[0]), "r"(b[1]))

// ---------------- split-bf16 tensor-core GEMM (3-pass, high precision) -------
// EPI==0: fp32 out. EPI==1: relu -> split bf16 out.
template <int EPI>
__global__ void __launch_bounds__(256)
mma_gemm(const __nv_bfloat16* __restrict__ Ahi, const __nv_bfloat16* __restrict__ Alo,
         const __nv_bfloat16* __restrict__ Whi, const __nv_bfloat16* __restrict__ Wlo,
         const float* __restrict__ bias,
         float* __restrict__ Cf,
         __nv_bfloat16* __restrict__ Chi, __nv_bfloat16* __restrict__ Clo,
         int M, int N, int K) {
    __shared__ __nv_bfloat16 sAh[BM][BKG + SPAD], sAl[BM][BKG + SPAD];
    __shared__ __nv_bfloat16 sBh[BN][BKG + SPAD], sBl[BN][BKG + SPAD];

    const int tid = threadIdx.x;
    const int m0 = blockIdx.y * BM;
    const int n0 = blockIdx.x * BN;
    const int warp = tid >> 5, lane = tid & 31;
    const int wm = (warp & 1) * 64;
    const int wn = (warp >> 1) * 32;
    const int g = lane >> 2, t = lane & 3;

    float c[4][4][4];
#pragma unroll
    for (int mt = 0; mt < 4; mt++)
#pragma unroll
        for (int nt = 0; nt < 4; nt++)
#pragma unroll
            for (int i = 0; i < 4; i++) c[mt][nt][i] = 0.f;

    const int lr = tid >> 2;
    const int lc = (tid & 3) * 8;

    for (int k0 = 0; k0 < K; k0 += BKG) {
#pragma unroll
        for (int rr = lr; rr < BM; rr += 64) {
            int gm = m0 + rr;
            uint4 vh = make_uint4(0, 0, 0, 0), vl = make_uint4(0, 0, 0, 0);
            if (gm < M) {
                vh = *(const uint4*)&Ahi[(size_t)gm * K + k0 + lc];
                vl = *(const uint4*)&Alo[(size_t)gm * K + k0 + lc];
            }
            *(uint4*)&sAh[rr][lc] = vh;
            *(uint4*)&sAl[rr][lc] = vl;
            int gn = n0 + rr;
            uint4 wh = make_uint4(0, 0, 0, 0), wl = make_uint4(0, 0, 0, 0);
            if (gn < N) {
                wh = *(const uint4*)&Whi[(size_t)gn * K + k0 + lc];
                wl = *(const uint4*)&Wlo[(size_t)gn * K + k0 + lc];
            }
            *(uint4*)&sBh[rr][lc] = wh;
            *(uint4*)&sBl[rr][lc] = wl;
        }
        __syncthreads();

#pragma unroll
        for (int kk = 0; kk < 2; kk++) {
            const int kb = kk * 16;
            uint32_t ah[4][4], al[4][4], bh[4][2], bl[4][2];
#pragma unroll
            for (int mt = 0; mt < 4; mt++) {
                int row = wm + mt * 16;
                ah[mt][0] = *(const uint32_t*)&sAh[row + g][kb + 2 * t];
                ah[mt][1] = *(const uint32_t*)&sAh[row + g + 8][kb + 2 * t];
                ah[mt][2] = *(const uint32_t*)&sAh[row + g][kb + 2 * t + 8];
                ah[mt][3] = *(const uint32_t*)&sAh[row + g + 8][kb + 2 * t + 8];
                al[mt][0] = *(const uint32_t*)&sAl[row + g][kb + 2 * t];
                al[mt][1] = *(const uint32_t*)&sAl[row + g + 8][kb + 2 * t];
                al[mt][2] = *(const uint32_t*)&sAl[row + g][kb + 2 * t + 8];
                al[mt][3] = *(const uint32_t*)&sAl[row + g + 8][kb + 2 * t + 8];
            }
#pragma unroll
            for (int nt = 0; nt < 4; nt++) {
                int col = wn + nt * 8 + g;
                bh[nt][0] = *(const uint32_t*)&sBh[col][kb + 2 * t];
                bh[nt][1] = *(const uint32_t*)&sBh[col][kb + 2 * t + 8];
                bl[nt][0] = *(const uint32_t*)&sBl[col][kb + 2 * t];
                bl[nt][1] = *(const uint32_t*)&sBl[col][kb + 2 * t + 8];
            }
#pragma unroll
            for (int mt = 0; mt < 4; mt++)
#pragma unroll
                for (int nt = 0; nt < 4; nt++) {
                    MMA_BF16(c[mt][nt], ah[mt], bh[nt]);
                    MMA_BF16(c[mt][nt], al[mt], bh[nt]);
                    MMA_BF16(c[mt][nt], ah[mt], bl[nt]);
                }
        }
        __syncthreads();
    }

#pragma unroll
    for (int mt = 0; mt < 4; mt++) {
#pragma unroll
        for (int nt = 0; nt < 4; nt++) {
            int mA = m0 + wm + mt * 16 + g;
            int nA = n0 + wn + nt * 8 + 2 * t;
            if (nA >= N) continue;
            float bv0 = bias[nA];
            float bv1 = (nA + 1 < N) ? bias[nA + 1] : 0.f;
#pragma unroll
            for (int half = 0; half < 2; half++) {
                int m = mA + half * 8;
                if (m >= M) continue;
                float v0 = c[mt][nt][half * 2 + 0] + bv0;
                float v1 = c[mt][nt][half * 2 + 1] + bv1;
                if (EPI == 0) {
                    Cf[(size_t)m * N + nA] = v0;
                    if (nA + 1 < N) Cf[(size_t)m * N + nA + 1] = v1;
                } else {
                    v0 = fmaxf(v0, 0.f);
                    v1 = fmaxf(v1, 0.f);
                    __nv_bfloat16 h0 = __float2bfloat16(v0);
                    __nv_bfloat16 h1 = __float2bfloat16(v1);
                    Chi[(size_t)m * N + nA] = h0;
                    Clo[(size_t)m * N + nA] = __float2bfloat16(v0 - __bfloat162float(h0));
                    if (nA + 1 < N) {
                        Chi[(size_t)m * N + nA + 1] = h1;
                        Clo[(size_t)m * N + nA + 1] = __float2bfloat16(v1 - __bfloat162float(h1));
                    }
                }
            }
        }
    }
}

// ---------------- single-pass fp16 tensor-core GEMM (edge network) ----------
// EPI==1: relu -> fp16 out.  EPI==2: fp16 out.
template <int EPI>
__global__ void __launch_bounds__(256)
hgemm(const __half* __restrict__ A, const __half* __restrict__ W,
      const float* __restrict__ bias, __half* __restrict__ C,
      int M, int N, int K) {
    __shared__ __half sA[BM][BKG + SPAD];
    __shared__ __half sB[BN][BKG + SPAD];

    const int tid = threadIdx.x;
    const int m0 = blockIdx.y * BM;
    const int n0 = blockIdx.x * BN;
    const int warp = tid >> 5, lane = tid & 31;
    const int wm = (warp & 1) * 64;
    const int wn = (warp >> 1) * 32;
    const int g = lane >> 2, t = lane & 3;

    float c[4][4][4];
#pragma unroll
    for (int mt = 0; mt < 4; mt++)
#pragma unroll
        for (int nt = 0; nt < 4; nt++)
#pragma unroll
            for (int i = 0; i < 4; i++) c[mt][nt][i] = 0.f;

    const int lr = tid >> 2;
    const int lc = (tid & 3) * 8;

    for (int k0 = 0; k0 < K; k0 += BKG) {
#pragma unroll
        for (int rr = lr; rr < BM; rr += 64) {
            int gm = m0 + rr;
            uint4 va = make_uint4(0, 0, 0, 0);
            if (gm < M) va = *(const uint4*)&A[(size_t)gm * K + k0 + lc];
            *(uint4*)&sA[rr][lc] = va;
            *(uint4*)&sB[rr][lc] = *(const uint4*)&W[(size_t)(n0 + rr) * K + k0 + lc];
        }
        __syncthreads();

#pragma unroll
        for (int kk = 0; kk < 2; kk++) {
            const int kb = kk * 16;
            uint32_t a[4][4], b[4][2];
#pragma unroll
            for (int mt = 0; mt < 4; mt++) {
                int row = wm + mt * 16;
                a[mt][0] = *(const uint32_t*)&sA[row + g][kb + 2 * t];
                a[mt][1] = *(const uint32_t*)&sA[row + g + 8][kb + 2 * t];
                a[mt][2] = *(const uint32_t*)&sA[row + g][kb + 2 * t + 8];
                a[mt][3] = *(const uint32_t*)&sA[row + g + 8][kb + 2 * t + 8];
            }
#pragma unroll
            for (int nt = 0; nt < 4; nt++) {
                int col = wn + nt * 8 + g;
                b[nt][0] = *(const uint32_t*)&sB[col][kb + 2 * t];
                b[nt][1] = *(const uint32_t*)&sB[col][kb + 2 * t + 8];
            }
#pragma unroll
            for (int mt = 0; mt < 4; mt++)
#pragma unroll
                for (int nt = 0; nt < 4; nt++) MMA_F16(c[mt][nt], a[mt], b[nt]);
        }
        __syncthreads();
    }

#pragma unroll
    for (int mt = 0; mt < 4; mt++) {
#pragma unroll
        for (int nt = 0; nt < 4; nt++) {
            int mA = m0 + wm + mt * 16 + g;
            int nA = n0 + wn + nt * 8 + 2 * t;
            float bv0 = bias[nA], bv1 = bias[nA + 1];
#pragma unroll
            for (int half = 0; half < 2; half++) {
                int m = mA + half * 8;
                if (m >= M) continue;
                float v0 = c[mt][nt][half * 2 + 0] + bv0;
                float v1 = c[mt][nt][half * 2 + 1] + bv1;
                if (EPI == 1) { v0 = fmaxf(v0, 0.f); v1 = fmaxf(v1, 0.f); }
                __half2* cp = (__half2*)&C[(size_t)m * N + nA];
                *cp = __floats2half2_rn(v0, v1);
            }
        }
    }
}

// ---------------- per-edge matvec (fp16 We, LDG.128) + scatter ---------------
// one warp per edge; lane loads uint4 (8 halves); warp-load covers 4 rows.
__global__ void __launch_bounds__(256)
msg_kernel(const float* __restrict__ h,
           const int* __restrict__ src, const int* __restrict__ dst,
           const __half* __restrict__ We,
           float* __restrict__ agg, int E) {
    int w = threadIdx.x >> 5;
    int lane = threadIdx.x & 31;
    int e = blockIdx.x * 8 + w;
    __shared__ float hs[8][HF];
    if (e < E) {
        int s = src[e];
        hs[w][lane] = h[s * HF + lane];
        hs[w][lane + 32] = h[s * HF + lane + 32];
    }
    __syncwarp();
    if (e >= E) return;

    const uint4* Wp = (const uint4*)(We + (size_t)e * (HF * HF));
    const int rsub = lane >> 3;       // row-within-quad
    float acc[8];
#pragma unroll
    for (int j = 0; j < 8; j++) acc[j] = 0.f;

#pragma unroll
    for (int i = 0; i < 16; i++) {
        uint4 v = Wp[i * 32 + lane];             // rows 4i..4i+3, 512B/warp
        float hv = hs[w][4 * i + rsub];
        const __half2* hp = (const __half2*)&v;
#pragma unroll
        for (int j = 0; j < 4; j++) {
            float2 f = __half22float2(hp[j]);
            acc[2 * j]     += hv * f.x;
            acc[2 * j + 1] += hv * f.y;
        }
    }
#pragma unroll
    for (int j = 0; j < 8; j++) {
        acc[j] += __shfl_xor_sync(0xffffffff, acc[j], 8);
        acc[j] += __shfl_xor_sync(0xffffffff, acc[j], 16);
    }
    if (lane < 8) {
        float* ap = agg + (size_t)dst[e] * HF + lane * 8;
#pragma unroll
        for (int j = 0; j < 8; j++) atomicAdd(ap + j, acc[j]);
    }
}

// ---------------- init: h-split into A buffer cols 64..127; zero agg --------
__global__ void init_state(const float* __restrict__ hbuf,
                           __nv_bfloat16* __restrict__ ah, __nv_bfloat16* __restrict__ al,
                           float* __restrict__ agg, int n) {
    int i = blockIdx.x * 256 + threadIdx.x;
    if (i >= n) return;
    int v = i >> 6, o = i & (HF - 1);
    float hv = hbuf[i];
    __nv_bfloat16 b = __float2bfloat16(hv);
    ah[v * 128 + HF + o] = b;
    al[v * 128 + HF + o] = __float2bfloat16(hv - __bfloat162float(b));
    agg[i] = 0.f;
}

// ---------------- prep: x = relu(agg+b_conv) -> split into A cols 0..63 -----
__global__ void prep_x(const float* __restrict__ agg, const float* __restrict__ b_conv,
                       __nv_bfloat16* __restrict__ ah, __nv_bfloat16* __restrict__ al,
                       int n) {
    int i = blockIdx.x * 256 + threadIdx.x;
    if (i >= n) return;
    int v = i >> 6, o = i & (HF - 1);
    float x = fmaxf(agg[i] + b_conv[o], 0.f);
    __nv_bfloat16 a = __float2bfloat16(x);
    ah[v * 128 + o] = a;
    al[v * 128 + o] = __float2bfloat16(x - __bfloat162float(a));
}

// ---------------- gates: GRU update + re-split h + zero agg ------------------
__global__ void gate_kernel(const float* __restrict__ gates,
                            float* __restrict__ hbuf,
                            __nv_bfloat16* __restrict__ ah, __nv_bfloat16* __restrict__ al,
                            float* __restrict__ agg, int n) {
    int i = blockIdx.x * 256 + threadIdx.x;
    if (i >= n) return;
    int v = i >> 6, o = i & (HF - 1);
    const float* gv = gates + (size_t)v * 4 * HF;
    float r = 1.f / (1.f + expf(-gv[o]));
    float z = 1.f / (1.f + expf(-gv[HF + o]));
    float nn = tanhf(gv[2 * HF + o] + r * gv[3 * HF + o]);
    float hv = hbuf[i];
    float h_new = (1.f - z) * nn + z * hv;
    hbuf[i] = h_new;
    __nv_bfloat16 b = __float2bfloat16(h_new);
    ah[v * 128 + HF + o] = b;
    al[v * 128 + HF + o] = __float2bfloat16(h_new - __bfloat162float(b));
    agg[i] = 0.f;
}

// ---------------- host launch ------------------------------------------------
extern "C" void kernel_launch(void* const* d_in, const int* in_sizes, int n_in,
                              void* d_out, int out_size) {
    const float* node_feats = (const float*)d_in[0];
    const float* edge_feats = (const float*)d_in[1];
    const int* src = (const int*)d_in[2];
    const int* dst = (const int*)d_in[3];
    const float* w_p1 = (const float*)d_in[4];
    const float* b_p1 = (const float*)d_in[5];
    const float* w_p2 = (const float*)d_in[6];
    const float* b_p2 = (const float*)d_in[7];
    const float* w_e1 = (const float*)d_in[8];
    const float* b_e1 = (const float*)d_in[9];
    const float* w_e2 = (const float*)d_in[10];
    const float* b_e2 = (const float*)d_in[11];
    const float* b_conv = (const float*)d_in[12];
    const float* w_ih = (const float*)d_in[13];
    const float* w_hh = (const float*)d_in[14];
    const float* b_ih = (const float*)d_in[15];
    const float* b_hh = (const float*)d_in[16];
    const float* w_d1 = (const float*)d_in[17];
    const float* b_d1 = (const float*)d_in[18];
    const float* w_d2 = (const float*)d_in[19];
    const float* b_d2 = (const float*)d_in[20];
    float* out = (float*)d_out;

    const int V = in_sizes[0] / NODE_IN;
    const int E = in_sizes[2];

    float *h_ptr, *agg_ptr, *gates_ptr, *wgf_ptr, *bg_ptr;
    __half *We_ptr, *ef16, *r16, *w116, *w216;
    __nv_bfloat16 *nh, *nl, *ph, *pl, *dh, *dl;
    __nv_bfloat16 *wp1h, *wp1l, *wp2h, *wp2l;
    __nv_bfloat16 *wd1h, *wd1l, *wd2h, *wd2l, *wgh, *wgl;
    cudaGetSymbolAddress((void**)&h_ptr, g_h);
    cudaGetSymbolAddress((void**)&We_ptr, g_We);
    cudaGetSymbolAddress((void**)&agg_ptr, g_agg);
    cudaGetSymbolAddress((void**)&gates_ptr, g_gates);
    cudaGetSymbolAddress((void**)&wgf_ptr, g_wgf);
    cudaGetSymbolAddress((void**)&bg_ptr, g_bg);
    cudaGetSymbolAddress((void**)&ef16, g_ef16);
    cudaGetSymbolAddress((void**)&r16, g_r16);
    cudaGetSymbolAddress((void**)&w116, g_w1_16);
    cudaGetSymbolAddress((void**)&w216, g_w2_16);
    cudaGetSymbolAddress((void**)&nh, g_nh);
    cudaGetSymbolAddress((void**)&nl, g_nl);
    cudaGetSymbolAddress((void**)&ph, g_ph);
    cudaGetSymbolAddress((void**)&pl, g_pl);
    cudaGetSymbolAddress((void**)&dh, g_dh);
    cudaGetSymbolAddress((void**)&dl, g_dl);
    cudaGetSymbolAddress((void**)&wp1h, g_wp1h);
    cudaGetSymbolAddress((void**)&wp1l, g_wp1l);
    cudaGetSymbolAddress((void**)&wp2h, g_wp2h);
    cudaGetSymbolAddress((void**)&wp2l, g_wp2l);
    cudaGetSymbolAddress((void**)&wd1h, g_wd1h);
    cudaGetSymbolAddress((void**)&wd1l, g_wd1l);
    cudaGetSymbolAddress((void**)&wd2h, g_wd2h);
    cudaGetSymbolAddress((void**)&wd2l, g_wd2l);
    cudaGetSymbolAddress((void**)&wgh, g_wgh);
    cudaGetSymbolAddress((void**)&wgl, g_wgl);

    // 0) convert / split inputs and weights; build fused GRU weight
    {
        int n;
        n = E * EDGE_IN;        tohalf_kernel<<<(n + 255) / 256, 256>>>(edge_feats, ef16, n);
        n = EDGE_HID * EDGE_IN; tohalf_kernel<<<(n + 255) / 256, 256>>>(w_e1, w116, n);
        n = HF * HF * EDGE_HID; tohalf_kernel<<<(n + 255) / 256, 256>>>(w_e2, w216, n);
        n = V * NODE_IN;        split_kernel<<<(n + 255) / 256, 256>>>(node_feats, nh, nl, n);
        n = HF * NODE_IN;       split_kernel<<<(n + 255) / 256, 256>>>(w_p1, wp1h, wp1l, n);
        n = HF * HF;            split_kernel<<<(n + 255) / 256, 256>>>(w_p2, wp2h, wp2l, n);
        n = HF * HF;            split_kernel<<<(n + 255) / 256, 256>>>(w_d1, wd1h, wd1l, n);
        n = OUTF * HF;          split_kernel<<<(n + 255) / 256, 256>>>(w_d2, wd2h, wd2l, n);
        build_gru_w<<<(256 * 128 + 255) / 256, 256>>>(w_ih, w_hh, b_ih, b_hh, wgf_ptr, bg_ptr);
        n = 256 * 128;          split_kernel<<<(n + 255) / 256, 256>>>(wgf_ptr, wgh, wgl, n);
    }

    const int mb_v = (V + BM - 1) / BM;
    const int mb_e = (E + BM - 1) / BM;
    const int nV = V * HF;

    // 1) project node feats -> g_h (fp32)
    mma_gemm<1><<<dim3(1, mb_v), 256>>>(nh, nl, wp1h, wp1l, b_p1,
                                        nullptr, ph, pl, V, HF, NODE_IN);
    mma_gemm<0><<<dim3(1, mb_v), 256>>>(ph, pl, wp2h, wp2l, b_p2,
                                        h_ptr, nullptr, nullptr, V, HF, HF);

    // 2) edge network -> We (fp16, single-pass fp16 mma)
    hgemm<1><<<dim3(EDGE_HID / BN, mb_e), 256>>>(ef16, w116, b_e1, r16, E, EDGE_HID, EDGE_IN);
    hgemm<2><<<dim3((HF * HF) / BN, mb_e), 256>>>(r16, w216, b_e2, We_ptr, E, HF * HF, EDGE_HID);

    // 3) init fused-A buffer with h, zero agg
    init_state<<<(nV + 255) / 256, 256>>>(h_ptr, nh, nl, agg_ptr, nV);

    // 4) message passing loop
    for (int s = 0; s < STEPS; s++) {
        msg_kernel<<<(E + 7) / 8, 256>>>(h_ptr, src, dst, We_ptr, agg_ptr, E);
        prep_x<<<(nV + 255) / 256, 256>>>(agg_ptr, b_conv, nh, nl, nV);
        mma_gemm<0><<<dim3(2, mb_v), 256>>>(nh, nl, wgh, wgl, bg_ptr,
                                            gates_ptr, nullptr, nullptr, V, 4 * HF, 128);
        gate_kernel<<<(nV + 255) / 256, 256>>>(gates_ptr, h_ptr, nh, nl, agg_ptr, nV);
    }

    // 5) decoder
    split_kernel<<<(nV + 255) / 256, 256>>>(h_ptr, ph, pl, nV);
    mma_gemm<1><<<dim3(1, mb_v), 256>>>(ph, pl, wd1h, wd1l, b_d1,
                                        nullptr, dh, dl, V, HF, HF);
    mma_gemm<0><<<dim3(1, mb_v), 256>>>(dh, dl, wd2h, wd2l, b_d2,
                                        out, nullptr, nullptr, V, OUTF, HF);
}

// round 17
// speedup vs baseline: 9.9674x; 1.0050x over previous
#include <cuda_runtime.h>
#include <cuda_bf16.h>
#include <cuda_fp16.h>
#include <math.h>
#include <stdint.h>

#define V_N 20000
#define E_N 100000
#define NODE_IN 128
#define EDGE_IN 128
#define HF 64
#define EDGE_HID 128
#define OUTF 64
#define STEPS 9

// ---------------- scratch (device globals; no allocations allowed) ----------
__device__ float g_h[V_N * HF];                    // node state fp32
__device__ __half g_We[(size_t)E_N * HF * HF];     // per-edge 64x64 matrices (fp16, 819 MB)
__device__ float g_agg[V_N * HF];                  // scatter accumulator
__device__ float g_gates[V_N * 4 * HF];            // fused GRU gates (V x 256)

// edge-network operands
__device__ __nv_bfloat16 g_efh[E_N * EDGE_IN], g_efl[E_N * EDGE_IN];
__device__ __half g_r16[E_N * EDGE_HID];
__device__ __nv_bfloat16 g_w1h[EDGE_HID * EDGE_IN], g_w1l[EDGE_HID * EDGE_IN];
__device__ __half g_w2_16[HF * HF * EDGE_HID];

// split-bf16 operand buffers (node path)
__device__ __nv_bfloat16 g_nh[V_N * 128], g_nl[V_N * 128];   // [x|h] per node (also node feats)
__device__ __nv_bfloat16 g_ph[V_N * HF], g_pl[V_N * HF];
__device__ __nv_bfloat16 g_dh[V_N * HF], g_dl[V_N * HF];
// split weights
__device__ __nv_bfloat16 g_wp1h[HF * NODE_IN], g_wp1l[HF * NODE_IN];
__device__ __nv_bfloat16 g_wp2h[HF * HF], g_wp2l[HF * HF];
__device__ __nv_bfloat16 g_wd1h[HF * HF], g_wd1l[HF * HF];
__device__ __nv_bfloat16 g_wd2h[OUTF * HF], g_wd2l[OUTF * HF];
// fused GRU weight: W' (256 x 128) and bias (256)
__device__ float g_wgf[256 * 128];
__device__ float g_bg[256];
__device__ __nv_bfloat16 g_wgh[256 * 128], g_wgl[256 * 128];

// ---------------- fp32 -> (hi, lo) bf16 split --------------------------------
__global__ void split_kernel(const float* __restrict__ x,
                             __nv_bfloat16* __restrict__ hi,
                             __nv_bfloat16* __restrict__ lo, int n) {
    int i = blockIdx.x * 256 + threadIdx.x;
    if (i < n) {
        float v = x[i];
        __nv_bfloat16 h = __float2bfloat16(v);
        hi[i] = h;
        lo[i] = __float2bfloat16(v - __bfloat162float(h));
    }
}

// ---------------- fp32 -> fp16 convert ---------------------------------------
__global__ void tohalf_kernel(const float* __restrict__ x, __half* __restrict__ y, int n) {
    int i = blockIdx.x * 256 + threadIdx.x;
    if (i < n) y[i] = __float2half_rn(x[i]);
}

// ---------------- build fused GRU weight W' (256x128) + bias ----------------
__global__ void build_gru_w(const float* __restrict__ w_ih, const float* __restrict__ w_hh,
                            const float* __restrict__ b_ih, const float* __restrict__ b_hh,
                            float* __restrict__ W, float* __restrict__ B) {
    int i = blockIdx.x * 256 + threadIdx.x;
    if (i >= 256 * 128) return;
    int j = i >> 7, k = i & 127;
    float v = 0.f;
    if (j < 128) {
        v = (k < HF) ? w_ih[j * HF + k] : w_hh[j * HF + (k - HF)];
    } else if (j < 192) {
        if (k < HF) v = w_ih[j * HF + k];
    } else {
        if (k >= HF) v = w_hh[(j - HF) * HF + (k - HF)];
    }
    W[i] = v;
    if (k == 0) {
        float b;
        if (j < 128) b = b_ih[j] + b_hh[j];
        else if (j < 192) b = b_ih[j];
        else b = b_hh[j - HF];
        B[j] = b;
    }
}

#define BM 128
#define BN 128
#define BKG 32
#define SPAD 8

#define MMA_BF16(c, a, b)                                                      \
    asm volatile(                                                              \
        "mma.sync.aligned.m16n8k16.row.col.f32.bf16.bf16.f32 "                 \
        "{%0,%1,%2,%3}, {%4,%5,%6,%7}, {%8,%9}, {%0,%1,%2,%3};"                \
        : "+f"(c[0]), "+f"(c[1]), "+f"(c[2]), "+f"(c[3])                       \
        : "r"(a[0]), "r"(a[1]), "r"(a[2]), "r"(a[3]), "r"(b[0]), "r"(b[1]))

#define MMA_F16(c, a, b)                                                       \
    asm volatile(                                                              \
        "mma.sync.aligned.m16n8k16.row.col.f32.f16.f16.f32 "                   \
        "{%0,%1,%2,%3}, {%4,%5,%6,%7}, {%8,%9}, {%0,%1,%2,%3};"                \
        : "+f"(c[0]), "+f"(c[1]), "+f"(c[2]), "+f"(c[3])                       \
        : "r"(a[0]), "r"(a[1]), "r"(a[2]), "r"(a[3]), "r"(b[0]), "r"(b[1]))

#define LDSM_X4(r0, r1, r2, r3, addr)                                          \
    asm volatile("ldmatrix.sync.aligned.m8n8.x4.shared.b16 {%0,%1,%2,%3},[%4];"\
                 : "=r"(r0), "=r"(r1), "=r"(r2), "=r"(r3) : "r"(addr))

// ---------------- split-bf16 tensor-core GEMM (3-pass, high precision) -------
// EPI==0: fp32 out. EPI==1: relu -> split bf16 out. EPI==3: relu -> fp16 out.
template <int EPI>
__global__ void __launch_bounds__(256)
mma_gemm(const __nv_bfloat16* __restrict__ Ahi, const __nv_bfloat16* __restrict__ Alo,
         const __nv_bfloat16* __restrict__ Whi, const __nv_bfloat16* __restrict__ Wlo,
         const float* __restrict__ bias,
         float* __restrict__ Cf,
         __nv_bfloat16* __restrict__ Chi, __nv_bfloat16* __restrict__ Clo,
         __half* __restrict__ Ch16,
         int M, int N, int K) {
    __shared__ __nv_bfloat16 sAh[BM][BKG + SPAD], sAl[BM][BKG + SPAD];
    __shared__ __nv_bfloat16 sBh[BN][BKG + SPAD], sBl[BN][BKG + SPAD];

    const int tid = threadIdx.x;
    const int m0 = blockIdx.y * BM;
    const int n0 = blockIdx.x * BN;
    const int warp = tid >> 5, lane = tid & 31;
    const int wm = (warp & 1) * 64;
    const int wn = (warp >> 1) * 32;
    const int g = lane >> 2, t = lane & 3;

    float c[4][4][4];
#pragma unroll
    for (int mt = 0; mt < 4; mt++)
#pragma unroll
        for (int nt = 0; nt < 4; nt++)
#pragma unroll
            for (int i = 0; i < 4; i++) c[mt][nt][i] = 0.f;

    const int lr = tid >> 2;
    const int lc = (tid & 3) * 8;

    for (int k0 = 0; k0 < K; k0 += BKG) {
#pragma unroll
        for (int rr = lr; rr < BM; rr += 64) {
            int gm = m0 + rr;
            uint4 vh = make_uint4(0, 0, 0, 0), vl = make_uint4(0, 0, 0, 0);
            if (gm < M) {
                vh = *(const uint4*)&Ahi[(size_t)gm * K + k0 + lc];
                vl = *(const uint4*)&Alo[(size_t)gm * K + k0 + lc];
            }
            *(uint4*)&sAh[rr][lc] = vh;
            *(uint4*)&sAl[rr][lc] = vl;
            int gn = n0 + rr;
            uint4 wh = make_uint4(0, 0, 0, 0), wl = make_uint4(0, 0, 0, 0);
            if (gn < N) {
                wh = *(const uint4*)&Whi[(size_t)gn * K + k0 + lc];
                wl = *(const uint4*)&Wlo[(size_t)gn * K + k0 + lc];
            }
            *(uint4*)&sBh[rr][lc] = wh;
            *(uint4*)&sBl[rr][lc] = wl;
        }
        __syncthreads();

#pragma unroll
        for (int kk = 0; kk < 2; kk++) {
            const int kb = kk * 16;
            uint32_t ah[4][4], al[4][4], bh[4][2], bl[4][2];
#pragma unroll
            for (int mt = 0; mt < 4; mt++) {
                int row = wm + mt * 16;
                ah[mt][0] = *(const uint32_t*)&sAh[row + g][kb + 2 * t];
                ah[mt][1] = *(const uint32_t*)&sAh[row + g + 8][kb + 2 * t];
                ah[mt][2] = *(const uint32_t*)&sAh[row + g][kb + 2 * t + 8];
                ah[mt][3] = *(const uint32_t*)&sAh[row + g + 8][kb + 2 * t + 8];
                al[mt][0] = *(const uint32_t*)&sAl[row + g][kb + 2 * t];
                al[mt][1] = *(const uint32_t*)&sAl[row + g + 8][kb + 2 * t];
                al[mt][2] = *(const uint32_t*)&sAl[row + g][kb + 2 * t + 8];
                al[mt][3] = *(const uint32_t*)&sAl[row + g + 8][kb + 2 * t + 8];
            }
#pragma unroll
            for (int nt = 0; nt < 4; nt++) {
                int col = wn + nt * 8 + g;
                bh[nt][0] = *(const uint32_t*)&sBh[col][kb + 2 * t];
                bh[nt][1] = *(const uint32_t*)&sBh[col][kb + 2 * t + 8];
                bl[nt][0] = *(const uint32_t*)&sBl[col][kb + 2 * t];
                bl[nt][1] = *(const uint32_t*)&sBl[col][kb + 2 * t + 8];
            }
#pragma unroll
            for (int mt = 0; mt < 4; mt++)
#pragma unroll
                for (int nt = 0; nt < 4; nt++) {
                    MMA_BF16(c[mt][nt], ah[mt], bh[nt]);
                    MMA_BF16(c[mt][nt], al[mt], bh[nt]);
                    MMA_BF16(c[mt][nt], ah[mt], bl[nt]);
                }
        }
        __syncthreads();
    }

#pragma unroll
    for (int mt = 0; mt < 4; mt++) {
#pragma unroll
        for (int nt = 0; nt < 4; nt++) {
            int mA = m0 + wm + mt * 16 + g;
            int nA = n0 + wn + nt * 8 + 2 * t;
            if (nA >= N) continue;
            float bv0 = bias[nA];
            float bv1 = (nA + 1 < N) ? bias[nA + 1] : 0.f;
#pragma unroll
            for (int half = 0; half < 2; half++) {
                int m = mA + half * 8;
                if (m >= M) continue;
                float v0 = c[mt][nt][half * 2 + 0] + bv0;
                float v1 = c[mt][nt][half * 2 + 1] + bv1;
                if (EPI == 0) {
                    Cf[(size_t)m * N + nA] = v0;
                    if (nA + 1 < N) Cf[(size_t)m * N + nA + 1] = v1;
                } else if (EPI == 3) {
                    v0 = fmaxf(v0, 0.f);
                    v1 = fmaxf(v1, 0.f);
                    Ch16[(size_t)m * N + nA] = __float2half_rn(v0);
                    if (nA + 1 < N) Ch16[(size_t)m * N + nA + 1] = __float2half_rn(v1);
                } else {
                    v0 = fmaxf(v0, 0.f);
                    v1 = fmaxf(v1, 0.f);
                    __nv_bfloat16 h0 = __float2bfloat16(v0);
                    __nv_bfloat16 h1 = __float2bfloat16(v1);
                    Chi[(size_t)m * N + nA] = h0;
                    Clo[(size_t)m * N + nA] = __float2bfloat16(v0 - __bfloat162float(h0));
                    if (nA + 1 < N) {
                        Chi[(size_t)m * N + nA + 1] = h1;
                        Clo[(size_t)m * N + nA + 1] = __float2bfloat16(v1 - __bfloat162float(h1));
                    }
                }
            }
        }
    }
}

// ---------------- single-pass fp16 tensor-core GEMM (edge layer 2) ----------
// ldmatrix-based fragment loads. EPI==2: fp16 out.
template <int EPI>
__global__ void __launch_bounds__(256)
hgemm(const __half* __restrict__ A, const __half* __restrict__ W,
      const float* __restrict__ bias, __half* __restrict__ C,
      int M, int N, int K) {
    __shared__ __half sA[BM][BKG + SPAD];
    __shared__ __half sB[BN][BKG + SPAD];

    const int tid = threadIdx.x;
    const int m0 = blockIdx.y * BM;
    const int n0 = blockIdx.x * BN;
    const int warp = tid >> 5, lane = tid & 31;
    const int wm = (warp & 1) * 64;
    const int wn = (warp >> 1) * 32;
    const int g = lane >> 2, t = lane & 3;

    float c[4][4][4];
#pragma unroll
    for (int mt = 0; mt < 4; mt++)
#pragma unroll
        for (int nt = 0; nt < 4; nt++)
#pragma unroll
            for (int i = 0; i < 4; i++) c[mt][nt][i] = 0.f;

    const int lr = tid >> 2;
    const int lc = (tid & 3) * 8;

    for (int k0 = 0; k0 < K; k0 += BKG) {
#pragma unroll
        for (int rr = lr; rr < BM; rr += 64) {
            int gm = m0 + rr;
            uint4 va = make_uint4(0, 0, 0, 0);
            if (gm < M) va = *(const uint4*)&A[(size_t)gm * K + k0 + lc];
            *(uint4*)&sA[rr][lc] = va;
            *(uint4*)&sB[rr][lc] = *(const uint4*)&W[(size_t)(n0 + rr) * K + k0 + lc];
        }
        __syncthreads();

#pragma unroll
        for (int kk = 0; kk < 2; kk++) {
            const int kb = kk * 16;
            uint32_t a[4][4], b[4][2];
            // A fragments: one ldmatrix.x4 per 16x16 tile
#pragma unroll
            for (int mt = 0; mt < 4; mt++) {
                int row = wm + mt * 16 + (lane & 15);
                uint32_t addr = (uint32_t)__cvta_generic_to_shared(
                    &sA[row][kb + 8 * (lane >> 4)]);
                LDSM_X4(a[mt][0], a[mt][1], a[mt][2], a[mt][3], addr);
            }
            // B fragments: one ldmatrix.x4 covers two n-tiles (4 matrices)
#pragma unroll
            for (int p = 0; p < 2; p++) {
                int q = lane >> 3;                       // matrix index 0..3
                int nrow = wn + (2 * p + (q >> 1)) * 8 + (lane & 7);
                int koff = kb + 8 * (q & 1);
                uint32_t addr = (uint32_t)__cvta_generic_to_shared(&sB[nrow][koff]);
                LDSM_X4(b[2 * p][0], b[2 * p][1], b[2 * p + 1][0], b[2 * p + 1][1], addr);
            }
#pragma unroll
            for (int mt = 0; mt < 4; mt++)
#pragma unroll
                for (int nt = 0; nt < 4; nt++) MMA_F16(c[mt][nt], a[mt], b[nt]);
        }
        __syncthreads();
    }

#pragma unroll
    for (int mt = 0; mt < 4; mt++) {
#pragma unroll
        for (int nt = 0; nt < 4; nt++) {
            int mA = m0 + wm + mt * 16 + g;
            int nA = n0 + wn + nt * 8 + 2 * t;
            float bv0 = bias[nA], bv1 = bias[nA + 1];
#pragma unroll
            for (int half = 0; half < 2; half++) {
                int m = mA + half * 8;
                if (m >= M) continue;
                float v0 = c[mt][nt][half * 2 + 0] + bv0;
                float v1 = c[mt][nt][half * 2 + 1] + bv1;
                if (EPI == 1) { v0 = fmaxf(v0, 0.f); v1 = fmaxf(v1, 0.f); }
                __half2* cp = (__half2*)&C[(size_t)m * N + nA];
                *cp = __floats2half2_rn(v0, v1);
            }
        }
    }
}

// ---------------- per-edge matvec (fp16 We, LDG.128) + scatter ---------------
__global__ void __launch_bounds__(256)
msg_kernel(const float* __restrict__ h,
           const int* __restrict__ src, const int* __restrict__ dst,
           const __half* __restrict__ We,
           float* __restrict__ agg, int E) {
    int w = threadIdx.x >> 5;
    int lane = threadIdx.x & 31;
    int e = blockIdx.x * 8 + w;
    __shared__ float hs[8][HF];
    if (e < E) {
        int s = src[e];
        hs[w][lane] = h[s * HF + lane];
        hs[w][lane + 32] = h[s * HF + lane + 32];
    }
    __syncwarp();
    if (e >= E) return;

    const uint4* Wp = (const uint4*)(We + (size_t)e * (HF * HF));
    const int rsub = lane >> 3;
    float acc[8];
#pragma unroll
    for (int j = 0; j < 8; j++) acc[j] = 0.f;

#pragma unroll
    for (int i = 0; i < 16; i++) {
        uint4 v = Wp[i * 32 + lane];
        float hv = hs[w][4 * i + rsub];
        const __half2* hp = (const __half2*)&v;
#pragma unroll
        for (int j = 0; j < 4; j++) {
            float2 f = __half22float2(hp[j]);
            acc[2 * j]     += hv * f.x;
            acc[2 * j + 1] += hv * f.y;
        }
    }
#pragma unroll
    for (int j = 0; j < 8; j++) {
        acc[j] += __shfl_xor_sync(0xffffffff, acc[j], 8);
        acc[j] += __shfl_xor_sync(0xffffffff, acc[j], 16);
    }
    if (lane < 8) {
        float* ap = agg + (size_t)dst[e] * HF + lane * 8;
#pragma unroll
        for (int j = 0; j < 8; j++) atomicAdd(ap + j, acc[j]);
    }
}

// ---------------- init: h-split into A buffer cols 64..127; zero agg --------
__global__ void init_state(const float* __restrict__ hbuf,
                           __nv_bfloat16* __restrict__ ah, __nv_bfloat16* __restrict__ al,
                           float* __restrict__ agg, int n) {
    int i = blockIdx.x * 256 + threadIdx.x;
    if (i >= n) return;
    int v = i >> 6, o = i & (HF - 1);
    float hv = hbuf[i];
    __nv_bfloat16 b = __float2bfloat16(hv);
    ah[v * 128 + HF + o] = b;
    al[v * 128 + HF + o] = __float2bfloat16(hv - __bfloat162float(b));
    agg[i] = 0.f;
}

// ---------------- prep: x = relu(agg+b_conv) -> split into A cols 0..63 -----
__global__ void prep_x(const float* __restrict__ agg, const float* __restrict__ b_conv,
                       __nv_bfloat16* __restrict__ ah, __nv_bfloat16* __restrict__ al,
                       int n) {
    int i = blockIdx.x * 256 + threadIdx.x;
    if (i >= n) return;
    int v = i >> 6, o = i & (HF - 1);
    float x = fmaxf(agg[i] + b_conv[o], 0.f);
    __nv_bfloat16 a = __float2bfloat16(x);
    ah[v * 128 + o] = a;
    al[v * 128 + o] = __float2bfloat16(x - __bfloat162float(a));
}

// ---------------- gates: GRU update + re-split h + zero agg ------------------
__global__ void gate_kernel(const float* __restrict__ gates,
                            float* __restrict__ hbuf,
                            __nv_bfloat16* __restrict__ ah, __nv_bfloat16* __restrict__ al,
                            float* __restrict__ agg, int n) {
    int i = blockIdx.x * 256 + threadIdx.x;
    if (i >= n) return;
    int v = i >> 6, o = i & (HF - 1);
    const float* gv = gates + (size_t)v * 4 * HF;
    float r = 1.f / (1.f + expf(-gv[o]));
    float z = 1.f / (1.f + expf(-gv[HF + o]));
    float nn = tanhf(gv[2 * HF + o] + r * gv[3 * HF + o]);
    float hv = hbuf[i];
    float h_new = (1.f - z) * nn + z * hv;
    hbuf[i] = h_new;
    __nv_bfloat16 b = __float2bfloat16(h_new);
    ah[v * 128 + HF + o] = b;
    al[v * 128 + HF + o] = __float2bfloat16(h_new - __bfloat162float(b));
    agg[i] = 0.f;
}

// ---------------- host launch ------------------------------------------------
extern "C" void kernel_launch(void* const* d_in, const int* in_sizes, int n_in,
                              void* d_out, int out_size) {
    const float* node_feats = (const float*)d_in[0];
    const float* edge_feats = (const float*)d_in[1];
    const int* src = (const int*)d_in[2];
    const int* dst = (const int*)d_in[3];
    const float* w_p1 = (const float*)d_in[4];
    const float* b_p1 = (const float*)d_in[5];
    const float* w_p2 = (const float*)d_in[6];
    const float* b_p2 = (const float*)d_in[7];
    const float* w_e1 = (const float*)d_in[8];
    const float* b_e1 = (const float*)d_in[9];
    const float* w_e2 = (const float*)d_in[10];
    const float* b_e2 = (const float*)d_in[11];
    const float* b_conv = (const float*)d_in[12];
    const float* w_ih = (const float*)d_in[13];
    const float* w_hh = (const float*)d_in[14];
    const float* b_ih = (const float*)d_in[15];
    const float* b_hh = (const float*)d_in[16];
    const float* w_d1 = (const float*)d_in[17];
    const float* b_d1 = (const float*)d_in[18];
    const float* w_d2 = (const float*)d_in[19];
    const float* b_d2 = (const float*)d_in[20];
    float* out = (float*)d_out;

    const int V = in_sizes[0] / NODE_IN;
    const int E = in_sizes[2];

    float *h_ptr, *agg_ptr, *gates_ptr, *wgf_ptr, *bg_ptr;
    __half *We_ptr, *r16, *w216;
    __nv_bfloat16 *efh, *efl, *w1h, *w1l;
    __nv_bfloat16 *nh, *nl, *ph, *pl, *dh, *dl;
    __nv_bfloat16 *wp1h, *wp1l, *wp2h, *wp2l;
    __nv_bfloat16 *wd1h, *wd1l, *wd2h, *wd2l, *wgh, *wgl;
    cudaGetSymbolAddress((void**)&h_ptr, g_h);
    cudaGetSymbolAddress((void**)&We_ptr, g_We);
    cudaGetSymbolAddress((void**)&agg_ptr, g_agg);
    cudaGetSymbolAddress((void**)&gates_ptr, g_gates);
    cudaGetSymbolAddress((void**)&wgf_ptr, g_wgf);
    cudaGetSymbolAddress((void**)&bg_ptr, g_bg);
    cudaGetSymbolAddress((void**)&efh, g_efh);
    cudaGetSymbolAddress((void**)&efl, g_efl);
    cudaGetSymbolAddress((void**)&r16, g_r16);
    cudaGetSymbolAddress((void**)&w1h, g_w1h);
    cudaGetSymbolAddress((void**)&w1l, g_w1l);
    cudaGetSymbolAddress((void**)&w216, g_w2_16);
    cudaGetSymbolAddress((void**)&nh, g_nh);
    cudaGetSymbolAddress((void**)&nl, g_nl);
    cudaGetSymbolAddress((void**)&ph, g_ph);
    cudaGetSymbolAddress((void**)&pl, g_pl);
    cudaGetSymbolAddress((void**)&dh, g_dh);
    cudaGetSymbolAddress((void**)&dl, g_dl);
    cudaGetSymbolAddress((void**)&wp1h, g_wp1h);
    cudaGetSymbolAddress((void**)&wp1l, g_wp1l);
    cudaGetSymbolAddress((void**)&wp2h, g_wp2h);
    cudaGetSymbolAddress((void**)&wp2l, g_wp2l);
    cudaGetSymbolAddress((void**)&wd1h, g_wd1h);
    cudaGetSymbolAddress((void**)&wd1l, g_wd1l);
    cudaGetSymbolAddress((void**)&wd2h, g_wd2h);
    cudaGetSymbolAddress((void**)&wd2l, g_wd2l);
    cudaGetSymbolAddress((void**)&wgh, g_wgh);
    cudaGetSymbolAddress((void**)&wgl, g_wgl);

    // 0) convert / split inputs and weights; build fused GRU weight
    {
        int n;
        n = E * EDGE_IN;        split_kernel<<<(n + 255) / 256, 256>>>(edge_feats, efh, efl, n);
        n = EDGE_HID * EDGE_IN; split_kernel<<<(n + 255) / 256, 256>>>(w_e1, w1h, w1l, n);
        n = HF * HF * EDGE_HID; tohalf_kernel<<<(n + 255) / 256, 256>>>(w_e2, w216, n);
        n = V * NODE_IN;        split_kernel<<<(n + 255) / 256, 256>>>(node_feats, nh, nl, n);
        n = HF * NODE_IN;       split_kernel<<<(n + 255) / 256, 256>>>(w_p1, wp1h, wp1l, n);
        n = HF * HF;            split_kernel<<<(n + 255) / 256, 256>>>(w_p2, wp2h, wp2l, n);
        n = HF * HF;            split_kernel<<<(n + 255) / 256, 256>>>(w_d1, wd1h, wd1l, n);
        n = OUTF * HF;          split_kernel<<<(n + 255) / 256, 256>>>(w_d2, wd2h, wd2l, n);
        build_gru_w<<<(256 * 128 + 255) / 256, 256>>>(w_ih, w_hh, b_ih, b_hh, wgf_ptr, bg_ptr);
        n = 256 * 128;          split_kernel<<<(n + 255) / 256, 256>>>(wgf_ptr, wgh, wgl, n);
    }

    const int mb_v = (V + BM - 1) / BM;
    const int mb_e = (E + BM - 1) / BM;
    const int nV = V * HF;

    // 1) project node feats -> g_h (fp32)
    mma_gemm<1><<<dim3(1, mb_v), 256>>>(nh, nl, wp1h, wp1l, b_p1,
                                        nullptr, ph, pl, nullptr, V, HF, NODE_IN);
    mma_gemm<0><<<dim3(1, mb_v), 256>>>(ph, pl, wp2h, wp2l, b_p2,
                                        h_ptr, nullptr, nullptr, nullptr, V, HF, HF);

    // 2) edge network: layer1 accurate 3-pass -> fp16 r; layer2 fp16 -> We
    mma_gemm<3><<<dim3(EDGE_HID / BN, mb_e), 256>>>(efh, efl, w1h, w1l, b_e1,
                                                    nullptr, nullptr, nullptr, r16,
                                                    E, EDGE_HID, EDGE_IN);
    hgemm<2><<<dim3((HF * HF) / BN, mb_e), 256>>>(r16, w216, b_e2, We_ptr, E, HF * HF, EDGE_HID);

    // 3) init fused-A buffer with h, zero agg
    init_state<<<(nV + 255) / 256, 256>>>(h_ptr, nh, nl, agg_ptr, nV);

    // 4) message passing loop
    for (int s = 0; s < STEPS; s++) {
        msg_kernel<<<(E + 7) / 8, 256>>>(h_ptr, src, dst, We_ptr, agg_ptr, E);
        prep_x<<<(nV + 255) / 256, 256>>>(agg_ptr, b_conv, nh, nl, nV);
        mma_gemm<0><<<dim3(2, mb_v), 256>>>(nh, nl, wgh, wgl, bg_ptr,
                                            gates_ptr, nullptr, nullptr, nullptr, V, 4 * HF, 128);
        gate_kernel<<<(nV + 255) / 256, 256>>>(gates_ptr, h_ptr, nh, nl, agg_ptr, nV);
    }

    // 5) decoder
    split_kernel<<<(nV + 255) / 256, 256>>>(h_ptr, ph, pl, nV);
    mma_gemm<1><<<dim3(1, mb_v), 256>>>(ph, pl, wd1h, wd1l, b_d1,
                                        nullptr, dh, dl, nullptr, V, HF, HF);
    mma_gemm<0><<<dim3(1, mb_v), 256>>>(dh, dl, wd2h, wd2l, b_d2,
                                        out, nullptr, nullptr, nullptr, V, OUTF, HF);
}